// round 3
// baseline (speedup 1.0000x reference)
#include <cuda_runtime.h>
#include <math.h>

#define Bb 8
#define Nn 2046
#define Dd 128
#define Jj 128
#define Ll 2
#define Cc 2048           // N + 2
#define BC (Bb*Cc)        // 16384
#define BN (Bb*Nn)        // 16368

// ---------------- device scratch (no allocation allowed) ----------------
__device__ float g_feats0[BC*Dd];
__device__ float g_feats1[BC*Dd];
__device__ float g_v[BC*Dd];
__device__ float g_seq[BC*Dd];
__device__ float g_weighted[BC*Dd];
__device__ float g_attnout[BC*Dd];
__device__ float g_qs[BC];
__device__ float g_ks[BC];
__device__ float g_uq[Dd];
__device__ float g_uk[Dd];
__device__ float g_c[2];
__device__ float g_part[Bb*16*Dd];

// ---------------- copy ops into feats rows [0,N) ----------------
__global__ void copy_ops_kernel(const float* __restrict__ ops, float* __restrict__ feats)
{
    int idx = blockIdx.x * 256 + threadIdx.x;   // BN*D = 2095104 = 8184*256
    int b = idx / (Nn*Dd);
    int rem = idx - b*(Nn*Dd);
    feats[(size_t)b*Cc*Dd + rem] = ops[idx];
}

__global__ void copyout_kernel(const float* __restrict__ feats, float* __restrict__ out)
{
    size_t idx = (size_t)blockIdx.x * 256 + threadIdx.x;   // BC*D = 2097152 = 8192*256
    out[idx] = feats[idx];
}

// ---------------- fused begin/end: gather-avg + [D,D] matvec ----------------
__global__ void __launch_bounds__(128) begin_end_kernel(
    const float* __restrict__ src,   // [B, C, D]
    const int* __restrict__ bidx, const int* __restrict__ eidx,
    const float* __restrict__ Wb, const float* __restrict__ bb,
    const float* __restrict__ We, const float* __restrict__ be,
    float* __restrict__ dst)         // [B, C, D]; writes row N+which
{
    int b = blockIdx.x, which = blockIdx.y, tx = threadIdx.x;
    const int* idx = which ? eidx : bidx;
    const float* W = which ? We : Wb;
    const float* bias = which ? be : bb;
    __shared__ float avg[128];
    float s = 0.f;
    #pragma unroll 8
    for (int j = 0; j < Jj; ++j) {
        int r = idx[b*Jj + j];
        s += src[((size_t)b*Cc + r)*Dd + tx];
    }
    avg[tx] = s * (1.f/Jj);
    __syncthreads();
    float o = 0.f;
    #pragma unroll 8
    for (int dd = 0; dd < Dd; ++dd)
        o += avg[dd] * W[dd*Dd + tx];
    dst[((size_t)b*Cc + Nn + which)*Dd + tx] = o + bias[tx];
}

// ---------------- precompute uq, uk, consts for one layer ----------------
__global__ void __launch_bounds__(128) precompute_kernel(
    const float* __restrict__ aw, const float* __restrict__ ab,
    const float* __restrict__ sw, const float* __restrict__ sb,
    float* __restrict__ uq, float* __restrict__ uk, float* __restrict__ cv)
{
    int d = threadIdx.x;
    float s1 = 0.f, s2 = 0.f;
    #pragma unroll 8
    for (int e = 0; e < 128; ++e) {
        s1 += aw[d*384 + e]       * sw[e];
        s2 += aw[d*384 + 128 + e] * sw[128 + e];
    }
    uq[d] = s1; uk[d] = s2;
    if (d == 0) {
        float c1 = 0.f, c2 = 0.f;
        for (int e = 0; e < 128; ++e) { c1 += ab[e]*sw[e]; c2 += ab[128+e]*sw[128+e]; }
        cv[0] = c1;
        cv[1] = c2 + sb[0];   // fold score bias into ks const
    }
}

// ---------------- qs/ks per row: one warp per row ----------------
__global__ void __launch_bounds__(256) qsks_kernel(
    const float* __restrict__ feats,
    const float* __restrict__ uq, const float* __restrict__ uk,
    const float* __restrict__ cv,
    float* __restrict__ qs, float* __restrict__ ks)
{
    int warp = threadIdx.x >> 5;
    int lane = threadIdx.x & 31;
    int m = blockIdx.x * 8 + warp;    // grid = BC/8
    float4 f = ((const float4*)(feats + (size_t)m*Dd))[lane];
    float4 q4 = ((const float4*)uq)[lane];
    float4 k4 = ((const float4*)uk)[lane];
    float dq = f.x*q4.x + f.y*q4.y + f.z*q4.z + f.w*q4.w;
    float dk = f.x*k4.x + f.y*k4.y + f.z*k4.z + f.w*k4.w;
    #pragma unroll
    for (int off = 16; off; off >>= 1) {
        dq += __shfl_down_sync(0xffffffffu, dq, off);
        dk += __shfl_down_sync(0xffffffffu, dk, off);
    }
    if (lane == 0) { qs[m] = dq + cv[0]; ks[m] = dk + cv[1]; }
}

// ---------------- generic 128-output SGEMM, 3 A-access modes ----------------
template<int MODE, int KTOT>
__global__ void __launch_bounds__(128) gemm128_kernel(
    const float* __restrict__ A,
    const float* __restrict__ A2,
    const float* __restrict__ W, int ws,
    const float* __restrict__ bias,
    float* __restrict__ out,
    const int* __restrict__ relations,
    int M)
{
    __shared__ float As[32*36];     // transposed: As[kk*36 + i]
    __shared__ float Ws[32*128];
    __shared__ int s_src[3][32];
    __shared__ int s_outrow[32];

    int tx = threadIdx.x;
    int m0 = blockIdx.x * 32;

    if (tx < 32) {
        int m = m0 + tx;
        if (MODE == 1) {
            if (m < M) {
                int b = m / Nn;
                int i = m - b*Nn;
                s_src[0][tx] = b*Cc + i;
                int rp = relations[(size_t)(b*Nn + i)*2 + 0];
                int rs = relations[(size_t)(b*Nn + i)*2 + 1];
                s_src[1][tx] = b*Cc + (rp < 0 ? Nn : rp);
                s_src[2][tx] = b*Cc + (rs < 0 ? Nn + 1 : rs);
                s_outrow[tx] = b*Cc + i;
            } else {
                s_src[0][tx] = 0; s_src[1][tx] = 0; s_src[2][tx] = 0;
                s_outrow[tx] = -1;
            }
        } else {
            s_outrow[tx] = (m < M) ? m : -1;
        }
    }
    __syncthreads();

    float acc[32];
    #pragma unroll
    for (int i = 0; i < 32; ++i) acc[i] = 0.f;

    const int NCHUNK = KTOT / 32;
    for (int kc = 0; kc < NCHUNK; ++kc) {
        int k0 = kc * 32;
        #pragma unroll 8
        for (int kk = 0; kk < 32; ++kk)
            Ws[kk*128 + tx] = W[(size_t)(k0 + kk)*ws + tx];
        int seg  = k0 >> 7;
        int col0 = k0 & 127;
        #pragma unroll
        for (int r = 0; r < 8; ++r) {
            int idx = tx + 128*r;
            int i  = idx >> 5;
            int kk = idx & 31;
            float v;
            if (MODE == 0) {
                v = A[(size_t)(m0 + i)*128 + col0 + kk];
            } else if (MODE == 1) {
                v = A[(size_t)s_src[seg][i]*128 + col0 + kk];
            } else {
                const float* src = seg ? A2 : A;
                v = src[(size_t)(m0 + i)*128 + col0 + kk];
            }
            As[kk*36 + i] = v;
        }
        __syncthreads();
        const float4* As4 = (const float4*)As;
        #pragma unroll 4
        for (int kk = 0; kk < 32; ++kk) {
            float w = Ws[kk*128 + tx];
            #pragma unroll
            for (int i4 = 0; i4 < 8; ++i4) {
                float4 a = As4[kk*9 + i4];
                acc[i4*4+0] += a.x * w;
                acc[i4*4+1] += a.y * w;
                acc[i4*4+2] += a.z * w;
                acc[i4*4+3] += a.w * w;
            }
        }
        __syncthreads();
    }
    float bv = bias[tx];
    #pragma unroll
    for (int i = 0; i < 32; ++i) {
        int orow = s_outrow[i];
        if (orow >= 0) out[(size_t)orow*128 + tx] = acc[i] + bv;
    }
}

// ---------------- fused masked GAT attention, flash-style v2 ----------------
// grid (C/32, B), block 128. 32 i-rows per block, 64-j tiles.
__global__ void __launch_bounds__(128) attn_kernel(
    const float* __restrict__ v,
    const float* __restrict__ qs, const float* __restrict__ ks,
    const float* __restrict__ mask,
    float* __restrict__ weighted)
{
    __shared__ float vs[64*128];      // 32 KB
    __shared__ float ps[64*36];       // ps[jj*36 + i], 4-way padded
    __shared__ float s_qs[32], s_ks[64];
    __shared__ float s_m[32], s_sum[32], s_scale[32];

    int b  = blockIdx.y;
    int i0 = blockIdx.x * 32;
    int tx = threadIdx.x;
    int row = tx >> 2, q = tx & 3;    // 4 lanes per row for reductions

    if (tx < 32) {
        s_qs[tx]  = qs[b*Cc + i0 + tx];
        s_m[tx]   = -1e30f;
        s_sum[tx] = 0.f;
    }

    float acc[32];
    #pragma unroll
    for (int i = 0; i < 32; ++i) acc[i] = 0.f;

    for (int j0 = 0; j0 < Cc; j0 += 64) {
        if (tx < 64) s_ks[tx] = ks[b*Cc + j0 + tx];
        // vectorized v tile load: 64 rows x 32 float4
        {
            const float4* v4 = (const float4*)(v + ((size_t)b*Cc + j0)*128);
            float4* vs4 = (float4*)vs;
            #pragma unroll
            for (int r = 0; r < 16; ++r)
                vs4[r*128 + tx] = v4[r*128 + tx];
        }
        __syncthreads();

        // logits -> ps (mask multiplies the leaky-relu score, pre-softmax)
        #pragma unroll
        for (int r = 0; r < 16; ++r) {
            int e  = r*128 + tx;
            int i  = e >> 6;
            int jj = e & 63;
            int gi = i0 + i;
            int j  = j0 + jj;
            float mval;
            if (gi < Nn && j < Nn) mval = mask[((size_t)b*Nn + gi)*Nn + j];
            else                   mval = (gi == j) ? 1.f : 0.f;
            float s  = s_qs[i] + s_ks[jj];
            float lr = s > 0.f ? s : 0.01f * s;
            ps[jj*36 + i] = lr * mval;
        }
        __syncthreads();

        // per-row running max (4 lanes per row)
        {
            float tm = -1e30f;
            #pragma unroll
            for (int t = 0; t < 16; ++t) tm = fmaxf(tm, ps[(q + 4*t)*36 + row]);
            tm = fmaxf(tm, __shfl_xor_sync(0xffffffffu, tm, 1));
            tm = fmaxf(tm, __shfl_xor_sync(0xffffffffu, tm, 2));
            if (q == 0) {
                float om = s_m[row];
                float nm = fmaxf(om, tm);
                s_scale[row] = __expf(om - nm);
                s_m[row] = nm;
            }
        }
        __syncthreads();

        // exp in place + per-row partial sums
        {
            float m = s_m[row];
            float ss = 0.f;
            #pragma unroll
            for (int t = 0; t < 16; ++t) {
                float e = __expf(ps[(q + 4*t)*36 + row] - m);
                ps[(q + 4*t)*36 + row] = e;
                ss += e;
            }
            ss += __shfl_xor_sync(0xffffffffu, ss, 1);
            ss += __shfl_xor_sync(0xffffffffu, ss, 2);
            if (q == 0) s_sum[row] = s_sum[row]*s_scale[row] + ss;
        }
        __syncthreads();

        #pragma unroll
        for (int i = 0; i < 32; ++i) acc[i] *= s_scale[i];
        #pragma unroll 4
        for (int jj = 0; jj < 64; ++jj) {
            float vv = vs[jj*128 + tx];
            const float4* p4 = (const float4*)(ps + jj*36);
            #pragma unroll
            for (int i4 = 0; i4 < 8; ++i4) {
                float4 a = p4[i4];
                acc[i4*4+0] += a.x * vv;
                acc[i4*4+1] += a.y * vv;
                acc[i4*4+2] += a.z * vv;
                acc[i4*4+3] += a.w * vv;
            }
        }
        __syncthreads();
    }

    #pragma unroll
    for (int i = 0; i < 32; ++i)
        weighted[((size_t)b*Cc + i0 + i)*128 + tx] = acc[i] / s_sum[i];
}

// ---------------- two-phase mean over C rows ----------------
__global__ void __launch_bounds__(128) mean1_kernel(const float* __restrict__ feats,
                                                    float* __restrict__ part)
{
    int b = blockIdx.x, p = blockIdx.y, tx = threadIdx.x;
    float s = 0.f;
    #pragma unroll 8
    for (int i = 0; i < Cc/16; ++i)
        s += feats[((size_t)b*Cc + p*(Cc/16) + i)*128 + tx];
    part[(b*16 + p)*128 + tx] = s;
}

__global__ void __launch_bounds__(128) mean2_kernel(const float* __restrict__ part,
                                                    float* __restrict__ out)
{
    int b = blockIdx.x, tx = threadIdx.x;
    float s = 0.f;
    #pragma unroll
    for (int p = 0; p < 16; ++p)
        s += part[(b*16 + p)*128 + tx];
    out[b*128 + tx] = s * (1.f/Cc);
}

// ---------------- host launcher ----------------
extern "C" void kernel_launch(void* const* d_in, const int* in_sizes, int n_in,
                              void* d_out, int out_size)
{
    const float* ops        = (const float*)d_in[0];
    const float* mask       = (const float*)d_in[1];
    const int*   relations  = (const int*)  d_in[2];
    const int*   begins     = (const int*)  d_in[3];
    const int*   ends       = (const int*)  d_in[4];
    const float* init_bp_w  = (const float*)d_in[5];
    const float* init_bp_b  = (const float*)d_in[6];
    const float* init_ep_w  = (const float*)d_in[7];
    const float* init_ep_b  = (const float*)d_in[8];
    const float* be_bp_w    = (const float*)d_in[9];
    const float* be_bp_b    = (const float*)d_in[10];
    const float* be_ep_w    = (const float*)d_in[11];
    const float* be_ep_b    = (const float*)d_in[12];
    const float* seq_mix_w  = (const float*)d_in[13];
    const float* seq_mix_b  = (const float*)d_in[14];
    const float* attn_w_w   = (const float*)d_in[15];
    const float* attn_w_b   = (const float*)d_in[16];
    const float* score_w    = (const float*)d_in[17];
    const float* score_b    = (const float*)d_in[18];
    const float* attn_out_w = (const float*)d_in[19];
    const float* attn_out_b = (const float*)d_in[20];
    const float* mix_w      = (const float*)d_in[21];
    const float* mix_b      = (const float*)d_in[22];
    float* out = (float*)d_out;

    float *p_f0, *p_f1, *p_v, *p_seq, *p_wt, *p_ao, *p_qs, *p_ks, *p_uq, *p_uk, *p_c, *p_part;
    cudaGetSymbolAddress((void**)&p_f0, g_feats0);
    cudaGetSymbolAddress((void**)&p_f1, g_feats1);
    cudaGetSymbolAddress((void**)&p_v,  g_v);
    cudaGetSymbolAddress((void**)&p_seq, g_seq);
    cudaGetSymbolAddress((void**)&p_wt, g_weighted);
    cudaGetSymbolAddress((void**)&p_ao, g_attnout);
    cudaGetSymbolAddress((void**)&p_qs, g_qs);
    cudaGetSymbolAddress((void**)&p_ks, g_ks);
    cudaGetSymbolAddress((void**)&p_uq, g_uq);
    cudaGetSymbolAddress((void**)&p_uk, g_uk);
    cudaGetSymbolAddress((void**)&p_c,  g_c);
    cudaGetSymbolAddress((void**)&p_part, g_part);

    // init: feats0 = [ops; begin; end]
    copy_ops_kernel<<<(BN*Dd)/256, 256>>>(ops, p_f0);
    begin_end_kernel<<<dim3(Bb, 2), 128>>>(p_f0, begins, ends,
                                           init_bp_w, init_bp_b, init_ep_w, init_ep_b,
                                           p_f0);

    for (int l = 0; l < Ll; ++l) {
        float* cur = (l == 0) ? p_f0 : p_f1;
        float* nxt = (l == 0) ? p_f1 : p_f0;

        precompute_kernel<<<1, 128>>>(attn_w_w + (size_t)l*128*384,
                                      attn_w_b + (size_t)l*384,
                                      score_w + (size_t)l*256,
                                      score_b + l,
                                      p_uq, p_uk, p_c);
        qsks_kernel<<<BC/8, 256>>>(cur, p_uq, p_uk, p_c, p_qs, p_ks);

        // v = feats @ Wv + bv
        gemm128_kernel<0,128><<<BC/32, 128>>>(cur, nullptr,
            attn_w_w + (size_t)l*128*384 + 256, 384,
            attn_w_b + (size_t)l*384 + 256,
            p_v, nullptr, BC);

        // in-layer begin/end -> seq rows N, N+1
        begin_end_kernel<<<dim3(Bb, 2), 128>>>(cur, begins, ends,
            be_bp_w + (size_t)l*128*128, be_bp_b + (size_t)l*128,
            be_ep_w + (size_t)l*128*128, be_ep_b + (size_t)l*128,
            p_seq);

        // mixed = [self, pred, succ] @ seq_mix_w[l] + b  -> seq rows [0, N)
        gemm128_kernel<1,384><<<(BN+31)/32, 128>>>(cur, nullptr,
            seq_mix_w + (size_t)l*384*128, 128,
            seq_mix_b + (size_t)l*128,
            p_seq, relations, BN);

        // fused masked attention -> weighted
        attn_kernel<<<dim3(Cc/32, Bb), 128>>>(p_v, p_qs, p_ks, mask, p_wt);

        // attn_out = weighted @ attn_out_w[l] + b
        gemm128_kernel<0,128><<<BC/32, 128>>>(p_wt, nullptr,
            attn_out_w + (size_t)l*128*128, 128,
            attn_out_b + (size_t)l*128,
            p_ao, nullptr, BC);

        // feats_next = [seq_feats, attn_out] @ mix_w[l] + b
        gemm128_kernel<2,256><<<BC/32, 128>>>(p_seq, p_ao,
            mix_w + (size_t)l*256*128, 128,
            mix_b + (size_t)l*128,
            nxt, nullptr, BC);
    }

    // outputs: mean [B,D] then feats [B,C,D]  (final feats is g_feats0 after L=2)
    mean1_kernel<<<dim3(Bb, 16), 128>>>(p_f0, p_part);
    mean2_kernel<<<Bb, 128>>>(p_part, out);
    copyout_kernel<<<(BC*Dd)/256, 256>>>(p_f0, out + Bb*Dd);
}

// round 5
// speedup vs baseline: 1.5752x; 1.5752x over previous
#include <cuda_runtime.h>
#include <math.h>
#include <stdint.h>

#define Bb 8
#define Nn 2046
#define Dd 128
#define Jj 128
#define Ll 2
#define Cc 2048
#define BC (Bb*Cc)
#define BN (Bb*Nn)

__device__ float g_feats0[BC*Dd];
__device__ float g_feats1[BC*Dd];
__device__ float g_v[BC*Dd];
__device__ float g_seq[BC*Dd];
__device__ float g_weighted[BC*Dd];
__device__ float g_attnout[BC*Dd];
__device__ float g_qs[BC];
__device__ float g_ks[BC];
__device__ float g_uq[Dd];
__device__ float g_uk[Dd];
__device__ float g_c[2];
__device__ float g_part[Bb*16*Dd];
__device__ float g_ksmax[Bb];

__device__ __forceinline__ uint32_t f2tf32(float x){
    uint32_t u; asm("cvt.rna.tf32.f32 %0, %1;" : "=r"(u) : "f"(x)); return u;
}
__device__ __forceinline__ void mma_tf32(float c[4], const uint32_t a[4], uint32_t b0, uint32_t b1){
    asm volatile("mma.sync.aligned.m16n8k8.row.col.f32.tf32.tf32.f32 "
        "{%0,%1,%2,%3}, {%4,%5,%6,%7}, {%8,%9}, {%0,%1,%2,%3};"
        : "+f"(c[0]), "+f"(c[1]), "+f"(c[2]), "+f"(c[3])
        : "r"(a[0]), "r"(a[1]), "r"(a[2]), "r"(a[3]), "r"(b0), "r"(b1));
}

__global__ void copy_ops_kernel(const float* __restrict__ ops, float* __restrict__ feats){
    int idx = blockIdx.x * 256 + threadIdx.x;
    int b = idx / (Nn*Dd);
    int rem = idx - b*(Nn*Dd);
    feats[(size_t)b*Cc*Dd + rem] = ops[idx];
}
__global__ void copyout_kernel(const float* __restrict__ f, float* __restrict__ o){
    size_t i = (size_t)blockIdx.x * 256 + threadIdx.x; o[i] = f[i];
}

__global__ void __launch_bounds__(128) begin_end_kernel(
    const float* __restrict__ src, const int* __restrict__ bidx, const int* __restrict__ eidx,
    const float* __restrict__ Wb, const float* __restrict__ bb,
    const float* __restrict__ We, const float* __restrict__ be, float* __restrict__ dst){
    int b = blockIdx.x, which = blockIdx.y, tx = threadIdx.x;
    const int* idx = which ? eidx : bidx;
    const float* W = which ? We : Wb;
    const float* bias = which ? be : bb;
    __shared__ float avg[128];
    float s = 0.f;
    #pragma unroll 8
    for (int j = 0; j < Jj; ++j) s += src[((size_t)b*Cc + idx[b*Jj + j])*Dd + tx];
    avg[tx] = s * (1.f/Jj);
    __syncthreads();
    float o = 0.f;
    #pragma unroll 8
    for (int dd = 0; dd < Dd; ++dd) o += avg[dd] * W[dd*Dd + tx];
    dst[((size_t)b*Cc + Nn + which)*Dd + tx] = o + bias[tx];
}

__global__ void __launch_bounds__(128) precompute_kernel(
    const float* __restrict__ aw, const float* __restrict__ ab,
    const float* __restrict__ sw, const float* __restrict__ sb,
    float* __restrict__ uq, float* __restrict__ uk, float* __restrict__ cv){
    int d = threadIdx.x;
    float s1 = 0.f, s2 = 0.f;
    #pragma unroll 8
    for (int e = 0; e < 128; ++e) {
        s1 += aw[d*384 + e] * sw[e];
        s2 += aw[d*384 + 128 + e] * sw[128 + e];
    }
    uq[d] = s1; uk[d] = s2;
    if (d == 0) {
        float c1 = 0.f, c2 = 0.f;
        for (int e = 0; e < 128; ++e) { c1 += ab[e]*sw[e]; c2 += ab[128+e]*sw[128+e]; }
        cv[0] = c1; cv[1] = c2 + sb[0];
    }
}

__global__ void __launch_bounds__(256) qsks_kernel(
    const float* __restrict__ feats, const float* __restrict__ uq, const float* __restrict__ uk,
    const float* __restrict__ cv, float* __restrict__ qs, float* __restrict__ ks){
    int warp = threadIdx.x >> 5, lane = threadIdx.x & 31;
    int m = blockIdx.x * 8 + warp;
    float4 f = ((const float4*)(feats + (size_t)m*Dd))[lane];
    float4 q4 = ((const float4*)uq)[lane];
    float4 k4 = ((const float4*)uk)[lane];
    float dq = f.x*q4.x + f.y*q4.y + f.z*q4.z + f.w*q4.w;
    float dk = f.x*k4.x + f.y*k4.y + f.z*k4.z + f.w*k4.w;
    #pragma unroll
    for (int off = 16; off; off >>= 1) {
        dq += __shfl_down_sync(0xffffffffu, dq, off);
        dk += __shfl_down_sync(0xffffffffu, dk, off);
    }
    if (lane == 0) { qs[m] = dq + cv[0]; ks[m] = dk + cv[1]; }
}

__global__ void __launch_bounds__(256) ksmax_kernel(const float* __restrict__ ks, float* __restrict__ km){
    int b = blockIdx.x, tx = threadIdx.x;
    __shared__ float sm[256];
    float m = -1e30f;
    for (int j = tx; j < Cc; j += 256) m = fmaxf(m, ks[b*Cc + j]);
    sm[tx] = m; __syncthreads();
    for (int s = 128; s; s >>= 1) { if (tx < s) sm[tx] = fmaxf(sm[tx], sm[tx+s]); __syncthreads(); }
    if (tx == 0) km[b] = sm[0];
}

template<int MODE, int KTOT>
__global__ void __launch_bounds__(128) gemm128_kernel(
    const float* __restrict__ A, const float* __restrict__ A2,
    const float* __restrict__ W, int ws, const float* __restrict__ bias,
    float* __restrict__ out, const int* __restrict__ relations, int M){
    __shared__ float As[32*36];
    __shared__ float Ws[32*128];
    __shared__ int s_src[3][32];
    __shared__ int s_outrow[32];
    int tx = threadIdx.x, m0 = blockIdx.x * 32;
    if (tx < 32) {
        int m = m0 + tx;
        if (MODE == 1) {
            if (m < M) {
                int b = m / Nn, i = m - b*Nn;
                s_src[0][tx] = b*Cc + i;
                int rp = relations[(size_t)(b*Nn + i)*2 + 0];
                int rs = relations[(size_t)(b*Nn + i)*2 + 1];
                s_src[1][tx] = b*Cc + (rp < 0 ? Nn : rp);
                s_src[2][tx] = b*Cc + (rs < 0 ? Nn + 1 : rs);
                s_outrow[tx] = b*Cc + i;
            } else { s_src[0][tx]=0; s_src[1][tx]=0; s_src[2][tx]=0; s_outrow[tx] = -1; }
        } else s_outrow[tx] = (m < M) ? m : -1;
    }
    __syncthreads();
    float acc[32];
    #pragma unroll
    for (int i = 0; i < 32; ++i) acc[i] = 0.f;
    for (int kc = 0; kc < KTOT/32; ++kc) {
        int k0 = kc * 32;
        #pragma unroll 8
        for (int kk = 0; kk < 32; ++kk) Ws[kk*128 + tx] = W[(size_t)(k0+kk)*ws + tx];
        int seg = k0 >> 7, col0 = k0 & 127;
        #pragma unroll
        for (int r = 0; r < 8; ++r) {
            int idx = tx + 128*r, i = idx >> 5, kk = idx & 31;
            float v;
            if (MODE == 0) v = A[(size_t)(m0+i)*128 + col0 + kk];
            else if (MODE == 1) v = A[(size_t)s_src[seg][i]*128 + col0 + kk];
            else { const float* s = seg ? A2 : A; v = s[(size_t)(m0+i)*128 + col0 + kk]; }
            As[kk*36 + i] = v;
        }
        __syncthreads();
        const float4* As4 = (const float4*)As;
        #pragma unroll 4
        for (int kk = 0; kk < 32; ++kk) {
            float w = Ws[kk*128 + tx];
            #pragma unroll
            for (int i4 = 0; i4 < 8; ++i4) {
                float4 a = As4[kk*9 + i4];
                acc[i4*4+0] += a.x*w; acc[i4*4+1] += a.y*w;
                acc[i4*4+2] += a.z*w; acc[i4*4+3] += a.w*w;
            }
        }
        __syncthreads();
    }
    float bv = bias[tx];
    #pragma unroll
    for (int i = 0; i < 32; ++i) {
        int o = s_outrow[i];
        if (o >= 0) out[(size_t)o*128 + tx] = acc[i] + bv;
    }
}

// ======== mma.sync tf32 attention: grid(16,B), 256 thr ========
// Block: 128 i-rows x 128 d-cols. Warp w: rows 16w..16w+15.
// P fragments computed in registers (no A smem); V hi/lo tiles in smem.
#define VSTRIDE 136
__global__ void __launch_bounds__(256) attn_mma_kernel(
    const float* __restrict__ v, const float* __restrict__ qs,
    const float* __restrict__ ks, const float* __restrict__ ksmax,
    const float* __restrict__ mask, float* __restrict__ weighted)
{
    __shared__ float vhi[32*VSTRIDE];
    __shared__ float vlo[32*VSTRIDE];
    __shared__ float s_ks[32];

    const int b = blockIdx.y, i0 = blockIdx.x*128;
    const int tid = threadIdx.x, w = tid>>5, lane = tid&31;
    const int g = lane>>2, l = lane&3;
    const int r0 = 16*w + g, r1 = r0 + 8;
    const int gi0 = i0 + r0, gi1 = i0 + r1;

    const float q0 = qs[b*Cc + gi0];
    const float q1 = qs[b*Cc + gi1];
    const float km = ksmax[b];
    float t0 = q0 + km; t0 = t0 > 0.f ? t0 : 0.01f*t0;
    float t1 = q1 + km; t1 = t1 > 0.f ? t1 : 0.01f*t1;
    const float M0 = fmaxf(0.f, t0);
    const float M1 = fmaxf(0.f, t1);
    float sum0 = 0.f, sum1 = 0.f;

    const float* mrow0 = mask + (size_t)b*Nn*Nn + (size_t)gi0*Nn;
    const float* mrow1 = mask + (size_t)b*Nn*Nn + (size_t)gi1*Nn;
    const bool in0 = gi0 < Nn, in1 = gi1 < Nn;

    float acc[16][4];
    #pragma unroll
    for (int nt = 0; nt < 16; ++nt) {
        acc[nt][0] = 0.f; acc[nt][1] = 0.f; acc[nt][2] = 0.f; acc[nt][3] = 0.f;
    }

    const int jr = tid >> 3;          // 0..31: V tile row
    const int cb = (tid & 7) * 16;    // col base (4 float4)

    for (int j0 = 0; j0 < Cc; j0 += 32) {
        __syncthreads();
        {   // fill V hi/lo tile + ks tile
            const float4* src = (const float4*)(v + ((size_t)(b*Cc + j0 + jr))*128 + cb);
            float* dh = vhi + jr*VSTRIDE + cb;
            float* dl = vlo + jr*VSTRIDE + cb;
            #pragma unroll
            for (int k4 = 0; k4 < 4; ++k4) {
                float4 x = src[k4];
                float hx = __uint_as_float(f2tf32(x.x));
                float hy = __uint_as_float(f2tf32(x.y));
                float hz = __uint_as_float(f2tf32(x.z));
                float hw = __uint_as_float(f2tf32(x.w));
                dh[k4*4+0] = hx; dh[k4*4+1] = hy; dh[k4*4+2] = hz; dh[k4*4+3] = hw;
                dl[k4*4+0] = __uint_as_float(f2tf32(x.x - hx));
                dl[k4*4+1] = __uint_as_float(f2tf32(x.y - hy));
                dl[k4*4+2] = __uint_as_float(f2tf32(x.z - hz));
                dl[k4*4+3] = __uint_as_float(f2tf32(x.w - hw));
            }
            if (tid < 32) s_ks[tid] = ks[b*Cc + j0 + tid];
        }
        __syncthreads();

        #pragma unroll
        for (int kc = 0; kc < 4; ++kc) {
            const int jA = j0 + kc*8 + l;
            const int jB = jA + 4;
            const float kA = s_ks[kc*8 + l];
            const float kB = s_ks[kc*8 + l + 4];
            float m00 = (in0 && jA < Nn) ? __ldg(mrow0 + jA) : ((gi0 == jA) ? 1.f : 0.f);
            float m01 = (in0 && jB < Nn) ? __ldg(mrow0 + jB) : ((gi0 == jB) ? 1.f : 0.f);
            float m10 = (in1 && jA < Nn) ? __ldg(mrow1 + jA) : ((gi1 == jA) ? 1.f : 0.f);
            float m11 = (in1 && jB < Nn) ? __ldg(mrow1 + jB) : ((gi1 == jB) ? 1.f : 0.f);
            float x;
            x = q0 + kA; x = x > 0.f ? x : 0.01f*x; float p00 = __expf(x*m00 - M0);
            x = q0 + kB; x = x > 0.f ? x : 0.01f*x; float p01 = __expf(x*m01 - M0);
            x = q1 + kA; x = x > 0.f ? x : 0.01f*x; float p10 = __expf(x*m10 - M1);
            x = q1 + kB; x = x > 0.f ? x : 0.01f*x; float p11 = __expf(x*m11 - M1);
            sum0 += p00 + p01;
            sum1 += p10 + p11;
            uint32_t ah[4], al[4];
            ah[0] = f2tf32(p00); al[0] = f2tf32(p00 - __uint_as_float(ah[0]));
            ah[1] = f2tf32(p10); al[1] = f2tf32(p10 - __uint_as_float(ah[1]));
            ah[2] = f2tf32(p01); al[2] = f2tf32(p01 - __uint_as_float(ah[2]));
            ah[3] = f2tf32(p11); al[3] = f2tf32(p11 - __uint_as_float(ah[3]));
            const float* ph  = vhi + (kc*8 + l)*VSTRIDE;
            const float* ph4 = vhi + (kc*8 + l + 4)*VSTRIDE;
            const float* pl  = vlo + (kc*8 + l)*VSTRIDE;
            const float* pl4 = vlo + (kc*8 + l + 4)*VSTRIDE;
            #pragma unroll
            for (int nt = 0; nt < 16; ++nt) {
                int dcol = nt*8 + g;
                uint32_t bh0 = __float_as_uint(ph[dcol]);
                uint32_t bh1 = __float_as_uint(ph4[dcol]);
                uint32_t bl0 = __float_as_uint(pl[dcol]);
                uint32_t bl1 = __float_as_uint(pl4[dcol]);
                mma_tf32(acc[nt], ah, bh0, bh1);
                mma_tf32(acc[nt], al, bh0, bh1);
                mma_tf32(acc[nt], ah, bl0, bl1);
            }
        }
    }

    sum0 += __shfl_xor_sync(0xffffffffu, sum0, 1);
    sum0 += __shfl_xor_sync(0xffffffffu, sum0, 2);
    sum1 += __shfl_xor_sync(0xffffffffu, sum1, 1);
    sum1 += __shfl_xor_sync(0xffffffffu, sum1, 2);
    float inv0 = 1.f / sum0, inv1 = 1.f / sum1;

    float* w0 = weighted + ((size_t)(b*Cc + gi0))*128;
    float* w1 = weighted + ((size_t)(b*Cc + gi1))*128;
    #pragma unroll
    for (int nt = 0; nt < 16; ++nt) {
        int col = nt*8 + 2*l;
        *(float2*)(w0 + col) = make_float2(acc[nt][0]*inv0, acc[nt][1]*inv0);
        *(float2*)(w1 + col) = make_float2(acc[nt][2]*inv1, acc[nt][3]*inv1);
    }
}

__global__ void __launch_bounds__(128) mean1_kernel(const float* __restrict__ f, float* __restrict__ part){
    int b = blockIdx.x, p = blockIdx.y, tx = threadIdx.x;
    float s = 0.f;
    #pragma unroll 8
    for (int i = 0; i < Cc/16; ++i) s += f[((size_t)b*Cc + p*(Cc/16) + i)*128 + tx];
    part[(b*16 + p)*128 + tx] = s;
}
__global__ void __launch_bounds__(128) mean2_kernel(const float* __restrict__ part, float* __restrict__ out){
    int b = blockIdx.x, tx = threadIdx.x;
    float s = 0.f;
    #pragma unroll
    for (int p = 0; p < 16; ++p) s += part[(b*16 + p)*128 + tx];
    out[b*128 + tx] = s * (1.f/Cc);
}

extern "C" void kernel_launch(void* const* d_in, const int* in_sizes, int n_in,
                              void* d_out, int out_size)
{
    const float* ops       = (const float*)d_in[0];
    const float* mask      = (const float*)d_in[1];
    const int*   relations = (const int*)d_in[2];
    const int*   begins    = (const int*)d_in[3];
    const int*   ends      = (const int*)d_in[4];
    const float* init_bp_w = (const float*)d_in[5];
    const float* init_bp_b = (const float*)d_in[6];
    const float* init_ep_w = (const float*)d_in[7];
    const float* init_ep_b = (const float*)d_in[8];
    const float* be_bp_w   = (const float*)d_in[9];
    const float* be_bp_b   = (const float*)d_in[10];
    const float* be_ep_w   = (const float*)d_in[11];
    const float* be_ep_b   = (const float*)d_in[12];
    const float* seq_mix_w = (const float*)d_in[13];
    const float* seq_mix_b = (const float*)d_in[14];
    const float* attn_w_w  = (const float*)d_in[15];
    const float* attn_w_b  = (const float*)d_in[16];
    const float* score_w   = (const float*)d_in[17];
    const float* score_b   = (const float*)d_in[18];
    const float* attn_out_w= (const float*)d_in[19];
    const float* attn_out_b= (const float*)d_in[20];
    const float* mix_w     = (const float*)d_in[21];
    const float* mix_b     = (const float*)d_in[22];
    float* out = (float*)d_out;

    float *p_f0,*p_f1,*p_v,*p_seq,*p_wt,*p_ao,*p_qs,*p_ks,*p_uq,*p_uk,*p_c,*p_part,*p_km;
    cudaGetSymbolAddress((void**)&p_f0, g_feats0);
    cudaGetSymbolAddress((void**)&p_f1, g_feats1);
    cudaGetSymbolAddress((void**)&p_v,  g_v);
    cudaGetSymbolAddress((void**)&p_seq, g_seq);
    cudaGetSymbolAddress((void**)&p_wt, g_weighted);
    cudaGetSymbolAddress((void**)&p_ao, g_attnout);
    cudaGetSymbolAddress((void**)&p_qs, g_qs);
    cudaGetSymbolAddress((void**)&p_ks, g_ks);
    cudaGetSymbolAddress((void**)&p_uq, g_uq);
    cudaGetSymbolAddress((void**)&p_uk, g_uk);
    cudaGetSymbolAddress((void**)&p_c,  g_c);
    cudaGetSymbolAddress((void**)&p_part, g_part);
    cudaGetSymbolAddress((void**)&p_km, g_ksmax);

    copy_ops_kernel<<<(BN*Dd)/256, 256>>>(ops, p_f0);
    begin_end_kernel<<<dim3(Bb,2), 128>>>(p_f0, begins, ends,
        init_bp_w, init_bp_b, init_ep_w, init_ep_b, p_f0);

    for (int l = 0; l < Ll; ++l) {
        float* cur = (l == 0) ? p_f0 : p_f1;
        float* nxt = (l == 0) ? p_f1 : p_f0;

        precompute_kernel<<<1, 128>>>(attn_w_w + (size_t)l*128*384, attn_w_b + (size_t)l*384,
                                      score_w + (size_t)l*256, score_b + l, p_uq, p_uk, p_c);
        qsks_kernel<<<BC/8, 256>>>(cur, p_uq, p_uk, p_c, p_qs, p_ks);
        ksmax_kernel<<<Bb, 256>>>(p_ks, p_km);

        gemm128_kernel<0,128><<<BC/32, 128>>>(cur, nullptr,
            attn_w_w + (size_t)l*128*384 + 256, 384, attn_w_b + (size_t)l*384 + 256,
            p_v, nullptr, BC);

        begin_end_kernel<<<dim3(Bb,2), 128>>>(cur, begins, ends,
            be_bp_w + (size_t)l*128*128, be_bp_b + (size_t)l*128,
            be_ep_w + (size_t)l*128*128, be_ep_b + (size_t)l*128, p_seq);

        gemm128_kernel<1,384><<<(BN+31)/32, 128>>>(cur, nullptr,
            seq_mix_w + (size_t)l*384*128, 128, seq_mix_b + (size_t)l*128,
            p_seq, relations, BN);

        attn_mma_kernel<<<dim3(Cc/128, Bb), 256>>>(p_v, p_qs, p_ks, p_km, mask, p_wt);

        gemm128_kernel<0,128><<<BC/32, 128>>>(p_wt, nullptr,
            attn_out_w + (size_t)l*128*128, 128, attn_out_b + (size_t)l*128,
            p_ao, nullptr, BC);

        gemm128_kernel<2,256><<<BC/32, 128>>>(p_seq, p_ao,
            mix_w + (size_t)l*256*128, 128, mix_b + (size_t)l*128,
            nxt, nullptr, BC);
    }

    mean1_kernel<<<dim3(Bb,16), 128>>>(p_f0, p_part);
    mean2_kernel<<<Bb, 128>>>(p_part, out);
    copyout_kernel<<<(BC*Dd)/256, 256>>>(p_f0, out + Bb*Dd);
}

// round 6
// speedup vs baseline: 1.8864x; 1.1976x over previous
#include <cuda_runtime.h>
#include <math.h>
#include <stdint.h>

#define Bb 8
#define Nn 2046
#define Dd 128
#define Jj 128
#define Ll 2
#define Cc 2048
#define BC (Bb*Cc)
#define BN (Bb*Nn)

__device__ float g_feats0[BC*Dd];
__device__ float g_feats1[BC*Dd];
__device__ float g_v[BC*Dd];
__device__ float g_seq[BC*Dd];
__device__ float g_weighted[BC*Dd];
__device__ float g_attnout[BC*Dd];
__device__ float g_qs[BC];
__device__ float g_ks[BC];
__device__ float g_uq[Dd];
__device__ float g_uk[Dd];
__device__ float g_c[2];
__device__ float g_part[Bb*16*Dd];
__device__ float g_ksmax[Bb];

__device__ __forceinline__ uint32_t f2tf32(float x){
    uint32_t u; asm("cvt.rna.tf32.f32 %0, %1;" : "=r"(u) : "f"(x)); return u;
}
__device__ __forceinline__ void mma_tf32(float c[4], const uint32_t a[4], uint32_t b0, uint32_t b1){
    asm volatile("mma.sync.aligned.m16n8k8.row.col.f32.tf32.tf32.f32 "
        "{%0,%1,%2,%3}, {%4,%5,%6,%7}, {%8,%9}, {%0,%1,%2,%3};"
        : "+f"(c[0]), "+f"(c[1]), "+f"(c[2]), "+f"(c[3])
        : "r"(a[0]), "r"(a[1]), "r"(a[2]), "r"(a[3]), "r"(b0), "r"(b1));
}

__global__ void copy_ops_kernel(const float* __restrict__ ops, float* __restrict__ feats){
    int idx = blockIdx.x * 256 + threadIdx.x;
    int b = idx / (Nn*Dd);
    int rem = idx - b*(Nn*Dd);
    feats[(size_t)b*Cc*Dd + rem] = ops[idx];
}
__global__ void copyout_kernel(const float* __restrict__ f, float* __restrict__ o){
    size_t i = (size_t)blockIdx.x * 256 + threadIdx.x; o[i] = f[i];
}

__global__ void __launch_bounds__(128) begin_end_kernel(
    const float* __restrict__ src, const int* __restrict__ bidx, const int* __restrict__ eidx,
    const float* __restrict__ Wb, const float* __restrict__ bb,
    const float* __restrict__ We, const float* __restrict__ be, float* __restrict__ dst){
    int b = blockIdx.x, which = blockIdx.y, tx = threadIdx.x;
    const int* idx = which ? eidx : bidx;
    const float* W = which ? We : Wb;
    const float* bias = which ? be : bb;
    __shared__ float avg[128];
    float s = 0.f;
    #pragma unroll 8
    for (int j = 0; j < Jj; ++j) s += src[((size_t)b*Cc + idx[b*Jj + j])*Dd + tx];
    avg[tx] = s * (1.f/Jj);
    __syncthreads();
    float o = 0.f;
    #pragma unroll 8
    for (int dd = 0; dd < Dd; ++dd) o += avg[dd] * W[dd*Dd + tx];
    dst[((size_t)b*Cc + Nn + which)*Dd + tx] = o + bias[tx];
}

__global__ void __launch_bounds__(128) precompute_kernel(
    const float* __restrict__ aw, const float* __restrict__ ab,
    const float* __restrict__ sw, const float* __restrict__ sb,
    float* __restrict__ uq, float* __restrict__ uk, float* __restrict__ cv){
    int d = threadIdx.x;
    float s1 = 0.f, s2 = 0.f;
    #pragma unroll 8
    for (int e = 0; e < 128; ++e) {
        s1 += aw[d*384 + e] * sw[e];
        s2 += aw[d*384 + 128 + e] * sw[128 + e];
    }
    uq[d] = s1; uk[d] = s2;
    if (d == 0) {
        float c1 = 0.f, c2 = 0.f;
        for (int e = 0; e < 128; ++e) { c1 += ab[e]*sw[e]; c2 += ab[128+e]*sw[128+e]; }
        cv[0] = c1; cv[1] = c2 + sb[0];
    }
}

__global__ void __launch_bounds__(256) qsks_kernel(
    const float* __restrict__ feats, const float* __restrict__ uq, const float* __restrict__ uk,
    const float* __restrict__ cv, float* __restrict__ qs, float* __restrict__ ks){
    int warp = threadIdx.x >> 5, lane = threadIdx.x & 31;
    int m = blockIdx.x * 8 + warp;
    float4 f = ((const float4*)(feats + (size_t)m*Dd))[lane];
    float4 q4 = ((const float4*)uq)[lane];
    float4 k4 = ((const float4*)uk)[lane];
    float dq = f.x*q4.x + f.y*q4.y + f.z*q4.z + f.w*q4.w;
    float dk = f.x*k4.x + f.y*k4.y + f.z*k4.z + f.w*k4.w;
    #pragma unroll
    for (int off = 16; off; off >>= 1) {
        dq += __shfl_down_sync(0xffffffffu, dq, off);
        dk += __shfl_down_sync(0xffffffffu, dk, off);
    }
    if (lane == 0) { qs[m] = dq + cv[0]; ks[m] = dk + cv[1]; }
}

__global__ void __launch_bounds__(256) ksmax_kernel(const float* __restrict__ ks, float* __restrict__ km){
    int b = blockIdx.x, tx = threadIdx.x;
    __shared__ float sm[256];
    float m = -1e30f;
    for (int j = tx; j < Cc; j += 256) m = fmaxf(m, ks[b*Cc + j]);
    sm[tx] = m; __syncthreads();
    for (int s = 128; s; s >>= 1) { if (tx < s) sm[tx] = fmaxf(sm[tx], sm[tx+s]); __syncthreads(); }
    if (tx == 0) km[b] = sm[0];
}

// ======== mma.sync tf32 GEMM: 128 rows x 128 outs per block, 256 thr ========
// MODE 0: plain rows. MODE 1: gather3 via relations (K=384). MODE 2: concat2 (K=256).
#define GSTRIDE 136
#define ASTRIDE 36
#define GEMM_SMEM ((128*ASTRIDE + 2*32*GSTRIDE) * 4)

template<int MODE, int KTOT>
__global__ void __launch_bounds__(256) gemm_mma_kernel(
    const float* __restrict__ A, const float* __restrict__ A2,
    const float* __restrict__ W, int ws, const float* __restrict__ bias,
    float* __restrict__ out, const int* __restrict__ relations)
{
    extern __shared__ float sm[];
    float* As  = sm;                   // 128 x 36
    float* Whi = sm + 128*ASTRIDE;     // 32 x 136
    float* Wlo = Whi + 32*GSTRIDE;     // 32 x 136
    __shared__ int s_src[3][128];
    __shared__ int s_out[128];

    const int tid = threadIdx.x, w = tid>>5, lane = tid&31;
    const int g = lane>>2, l = lane&3;
    const int m0 = blockIdx.x * 128;

    if (tid < 128) {
        int m = m0 + tid;
        if (MODE == 1) {
            int b = m >> 11;
            int i = m & 2047;
            if (i < Nn) {
                s_src[0][tid] = b*Cc + i;
                int rp = relations[(size_t)(b*Nn + i)*2 + 0];
                int rs = relations[(size_t)(b*Nn + i)*2 + 1];
                s_src[1][tid] = b*Cc + (rp < 0 ? Nn : rp);
                s_src[2][tid] = b*Cc + (rs < 0 ? Nn + 1 : rs);
                s_out[tid] = m;
            } else {
                s_src[0][tid] = b*Cc; s_src[1][tid] = b*Cc; s_src[2][tid] = b*Cc;
                s_out[tid] = -1;
            }
        } else {
            s_out[tid] = m;
        }
    }

    float acc[16][4];
    #pragma unroll
    for (int nt = 0; nt < 16; ++nt) {
        acc[nt][0]=0.f; acc[nt][1]=0.f; acc[nt][2]=0.f; acc[nt][3]=0.f;
    }

    const int jr = tid>>3, cb = (tid&7)*16;     // W staging coords
    const int ar = tid>>1, ao = (tid&1)*16;     // A staging coords

    for (int k0 = 0; k0 < KTOT; k0 += 32) {
        __syncthreads();
        {   // stage W hi/lo (rows k0+jr, 16 cols at cb)
            const float* wsrc = W + (size_t)(k0 + jr)*ws + cb;
            float* dh = Whi + jr*GSTRIDE + cb;
            float* dl = Wlo + jr*GSTRIDE + cb;
            #pragma unroll
            for (int c = 0; c < 4; ++c) {
                float4 x = *(const float4*)(wsrc + 4*c);
                float hx = __uint_as_float(f2tf32(x.x));
                float hy = __uint_as_float(f2tf32(x.y));
                float hz = __uint_as_float(f2tf32(x.z));
                float hw = __uint_as_float(f2tf32(x.w));
                dh[4*c+0]=hx; dh[4*c+1]=hy; dh[4*c+2]=hz; dh[4*c+3]=hw;
                dl[4*c+0]=__uint_as_float(f2tf32(x.x-hx));
                dl[4*c+1]=__uint_as_float(f2tf32(x.y-hy));
                dl[4*c+2]=__uint_as_float(f2tf32(x.z-hz));
                dl[4*c+3]=__uint_as_float(f2tf32(x.w-hw));
            }
        }
        {   // stage A fp32 (row ar, half ao)
            const float* asrc;
            if (MODE == 0) {
                asrc = A + (size_t)(m0 + ar)*128 + k0 + ao;
            } else if (MODE == 1) {
                int seg = k0 >> 7, col = k0 & 127;
                asrc = A + (size_t)s_src[seg][ar]*128 + col + ao;
            } else {
                int seg = k0 >> 7, col = k0 & 127;
                const float* base = seg ? A2 : A;
                asrc = base + (size_t)(m0 + ar)*128 + col + ao;
            }
            float* d = As + ar*ASTRIDE + ao;
            #pragma unroll
            for (int c = 0; c < 4; ++c)
                *(float4*)(d + 4*c) = *(const float4*)(asrc + 4*c);
        }
        __syncthreads();

        #pragma unroll
        for (int kc = 0; kc < 4; ++kc) {
            const float* ap  = As + (16*w + g)*ASTRIDE + kc*8;
            const float* ap8 = ap + 8*ASTRIDE;
            float a00 = ap[l],   a10 = ap8[l];
            float a01 = ap[l+4], a11 = ap8[l+4];
            uint32_t ahf[4], alf[4];
            ahf[0]=f2tf32(a00); alf[0]=f2tf32(a00-__uint_as_float(ahf[0]));
            ahf[1]=f2tf32(a10); alf[1]=f2tf32(a10-__uint_as_float(ahf[1]));
            ahf[2]=f2tf32(a01); alf[2]=f2tf32(a01-__uint_as_float(ahf[2]));
            ahf[3]=f2tf32(a11); alf[3]=f2tf32(a11-__uint_as_float(ahf[3]));
            const float* ph  = Whi + (kc*8 + l)*GSTRIDE;
            const float* ph4 = Whi + (kc*8 + l + 4)*GSTRIDE;
            const float* pl  = Wlo + (kc*8 + l)*GSTRIDE;
            const float* pl4 = Wlo + (kc*8 + l + 4)*GSTRIDE;
            #pragma unroll
            for (int nt = 0; nt < 16; ++nt) {
                int dcol = nt*8 + g;
                uint32_t bh0 = __float_as_uint(ph[dcol]);
                uint32_t bh1 = __float_as_uint(ph4[dcol]);
                uint32_t bl0 = __float_as_uint(pl[dcol]);
                uint32_t bl1 = __float_as_uint(pl4[dcol]);
                mma_tf32(acc[nt], ahf, bh0, bh1);
                mma_tf32(acc[nt], alf, bh0, bh1);
                mma_tf32(acc[nt], ahf, bl0, bl1);
            }
        }
    }

    const int r0 = 16*w + g;
    const int o0 = s_out[r0], o1 = s_out[r0 + 8];
    float* w0 = out + (size_t)o0*128;
    float* w1 = out + (size_t)o1*128;
    #pragma unroll
    for (int nt = 0; nt < 16; ++nt) {
        int col = nt*8 + 2*l;
        float b0 = __ldg(bias + col), b1 = __ldg(bias + col + 1);
        if (o0 >= 0) *(float2*)(w0 + col) = make_float2(acc[nt][0]+b0, acc[nt][1]+b1);
        if (o1 >= 0) *(float2*)(w1 + col) = make_float2(acc[nt][2]+b0, acc[nt][3]+b1);
    }
}

// ======== mma.sync tf32 attention: grid(16,B), 256 thr ========
#define VSTRIDE 136
__global__ void __launch_bounds__(256) attn_mma_kernel(
    const float* __restrict__ v, const float* __restrict__ qs,
    const float* __restrict__ ks, const float* __restrict__ ksmax,
    const float* __restrict__ mask, float* __restrict__ weighted)
{
    __shared__ float vhi[32*VSTRIDE];
    __shared__ float vlo[32*VSTRIDE];
    __shared__ float s_ks[32];

    const int b = blockIdx.y, i0 = blockIdx.x*128;
    const int tid = threadIdx.x, w = tid>>5, lane = tid&31;
    const int g = lane>>2, l = lane&3;
    const int r0 = 16*w + g, r1 = r0 + 8;
    const int gi0 = i0 + r0, gi1 = i0 + r1;

    const float q0 = qs[b*Cc + gi0];
    const float q1 = qs[b*Cc + gi1];
    const float km = ksmax[b];
    float t0 = q0 + km; t0 = t0 > 0.f ? t0 : 0.01f*t0;
    float t1 = q1 + km; t1 = t1 > 0.f ? t1 : 0.01f*t1;
    const float M0 = fmaxf(0.f, t0);
    const float M1 = fmaxf(0.f, t1);
    float sum0 = 0.f, sum1 = 0.f;

    const float* mrow0 = mask + (size_t)b*Nn*Nn + (size_t)gi0*Nn;
    const float* mrow1 = mask + (size_t)b*Nn*Nn + (size_t)gi1*Nn;
    const bool in0 = gi0 < Nn, in1 = gi1 < Nn;

    float acc[16][4];
    #pragma unroll
    for (int nt = 0; nt < 16; ++nt) {
        acc[nt][0]=0.f; acc[nt][1]=0.f; acc[nt][2]=0.f; acc[nt][3]=0.f;
    }

    const int jr = tid >> 3;
    const int cb = (tid & 7) * 16;

    for (int j0 = 0; j0 < Cc; j0 += 32) {
        __syncthreads();
        {
            const float4* src = (const float4*)(v + ((size_t)(b*Cc + j0 + jr))*128 + cb);
            float* dh = vhi + jr*VSTRIDE + cb;
            float* dl = vlo + jr*VSTRIDE + cb;
            #pragma unroll
            for (int k4 = 0; k4 < 4; ++k4) {
                float4 x = src[k4];
                float hx = __uint_as_float(f2tf32(x.x));
                float hy = __uint_as_float(f2tf32(x.y));
                float hz = __uint_as_float(f2tf32(x.z));
                float hw = __uint_as_float(f2tf32(x.w));
                dh[k4*4+0]=hx; dh[k4*4+1]=hy; dh[k4*4+2]=hz; dh[k4*4+3]=hw;
                dl[k4*4+0]=__uint_as_float(f2tf32(x.x-hx));
                dl[k4*4+1]=__uint_as_float(f2tf32(x.y-hy));
                dl[k4*4+2]=__uint_as_float(f2tf32(x.z-hz));
                dl[k4*4+3]=__uint_as_float(f2tf32(x.w-hw));
            }
            if (tid < 32) s_ks[tid] = ks[b*Cc + j0 + tid];
        }
        __syncthreads();

        #pragma unroll
        for (int kc = 0; kc < 4; ++kc) {
            const int jA = j0 + kc*8 + l;
            const int jB = jA + 4;
            const float kA = s_ks[kc*8 + l];
            const float kB = s_ks[kc*8 + l + 4];
            float m00 = (in0 && jA < Nn) ? __ldg(mrow0 + jA) : ((gi0 == jA) ? 1.f : 0.f);
            float m01 = (in0 && jB < Nn) ? __ldg(mrow0 + jB) : ((gi0 == jB) ? 1.f : 0.f);
            float m10 = (in1 && jA < Nn) ? __ldg(mrow1 + jA) : ((gi1 == jA) ? 1.f : 0.f);
            float m11 = (in1 && jB < Nn) ? __ldg(mrow1 + jB) : ((gi1 == jB) ? 1.f : 0.f);
            float x;
            x = q0 + kA; x = x > 0.f ? x : 0.01f*x; float p00 = __expf(x*m00 - M0);
            x = q0 + kB; x = x > 0.f ? x : 0.01f*x; float p01 = __expf(x*m01 - M0);
            x = q1 + kA; x = x > 0.f ? x : 0.01f*x; float p10 = __expf(x*m10 - M1);
            x = q1 + kB; x = x > 0.f ? x : 0.01f*x; float p11 = __expf(x*m11 - M1);
            sum0 += p00 + p01;
            sum1 += p10 + p11;
            uint32_t ah[4], al[4];
            ah[0] = f2tf32(p00); al[0] = f2tf32(p00 - __uint_as_float(ah[0]));
            ah[1] = f2tf32(p10); al[1] = f2tf32(p10 - __uint_as_float(ah[1]));
            ah[2] = f2tf32(p01); al[2] = f2tf32(p01 - __uint_as_float(ah[2]));
            ah[3] = f2tf32(p11); al[3] = f2tf32(p11 - __uint_as_float(ah[3]));
            const float* ph  = vhi + (kc*8 + l)*VSTRIDE;
            const float* ph4 = vhi + (kc*8 + l + 4)*VSTRIDE;
            const float* pl  = vlo + (kc*8 + l)*VSTRIDE;
            const float* pl4 = vlo + (kc*8 + l + 4)*VSTRIDE;
            #pragma unroll
            for (int nt = 0; nt < 16; ++nt) {
                int dcol = nt*8 + g;
                uint32_t bh0 = __float_as_uint(ph[dcol]);
                uint32_t bh1 = __float_as_uint(ph4[dcol]);
                uint32_t bl0 = __float_as_uint(pl[dcol]);
                uint32_t bl1 = __float_as_uint(pl4[dcol]);
                mma_tf32(acc[nt], ah, bh0, bh1);
                mma_tf32(acc[nt], al, bh0, bh1);
                mma_tf32(acc[nt], ah, bl0, bl1);
            }
        }
    }

    sum0 += __shfl_xor_sync(0xffffffffu, sum0, 1);
    sum0 += __shfl_xor_sync(0xffffffffu, sum0, 2);
    sum1 += __shfl_xor_sync(0xffffffffu, sum1, 1);
    sum1 += __shfl_xor_sync(0xffffffffu, sum1, 2);
    float inv0 = 1.f / sum0, inv1 = 1.f / sum1;

    float* w0 = weighted + ((size_t)(b*Cc + gi0))*128;
    float* w1 = weighted + ((size_t)(b*Cc + gi1))*128;
    #pragma unroll
    for (int nt = 0; nt < 16; ++nt) {
        int col = nt*8 + 2*l;
        *(float2*)(w0 + col) = make_float2(acc[nt][0]*inv0, acc[nt][1]*inv0);
        *(float2*)(w1 + col) = make_float2(acc[nt][2]*inv1, acc[nt][3]*inv1);
    }
}

__global__ void __launch_bounds__(128) mean1_kernel(const float* __restrict__ f, float* __restrict__ part){
    int b = blockIdx.x, p = blockIdx.y, tx = threadIdx.x;
    float s = 0.f;
    #pragma unroll 8
    for (int i = 0; i < Cc/16; ++i) s += f[((size_t)b*Cc + p*(Cc/16) + i)*128 + tx];
    part[(b*16 + p)*128 + tx] = s;
}
__global__ void __launch_bounds__(128) mean2_kernel(const float* __restrict__ part, float* __restrict__ out){
    int b = blockIdx.x, tx = threadIdx.x;
    float s = 0.f;
    #pragma unroll
    for (int p = 0; p < 16; ++p) s += part[(b*16 + p)*128 + tx];
    out[b*128 + tx] = s * (1.f/Cc);
}

extern "C" void kernel_launch(void* const* d_in, const int* in_sizes, int n_in,
                              void* d_out, int out_size)
{
    const float* ops       = (const float*)d_in[0];
    const float* mask      = (const float*)d_in[1];
    const int*   relations = (const int*)d_in[2];
    const int*   begins    = (const int*)d_in[3];
    const int*   ends      = (const int*)d_in[4];
    const float* init_bp_w = (const float*)d_in[5];
    const float* init_bp_b = (const float*)d_in[6];
    const float* init_ep_w = (const float*)d_in[7];
    const float* init_ep_b = (const float*)d_in[8];
    const float* be_bp_w   = (const float*)d_in[9];
    const float* be_bp_b   = (const float*)d_in[10];
    const float* be_ep_w   = (const float*)d_in[11];
    const float* be_ep_b   = (const float*)d_in[12];
    const float* seq_mix_w = (const float*)d_in[13];
    const float* seq_mix_b = (const float*)d_in[14];
    const float* attn_w_w  = (const float*)d_in[15];
    const float* attn_w_b  = (const float*)d_in[16];
    const float* score_w   = (const float*)d_in[17];
    const float* score_b   = (const float*)d_in[18];
    const float* attn_out_w= (const float*)d_in[19];
    const float* attn_out_b= (const float*)d_in[20];
    const float* mix_w     = (const float*)d_in[21];
    const float* mix_b     = (const float*)d_in[22];
    float* out = (float*)d_out;

    float *p_f0,*p_f1,*p_v,*p_seq,*p_wt,*p_ao,*p_qs,*p_ks,*p_uq,*p_uk,*p_c,*p_part,*p_km;
    cudaGetSymbolAddress((void**)&p_f0, g_feats0);
    cudaGetSymbolAddress((void**)&p_f1, g_feats1);
    cudaGetSymbolAddress((void**)&p_v,  g_v);
    cudaGetSymbolAddress((void**)&p_seq, g_seq);
    cudaGetSymbolAddress((void**)&p_wt, g_weighted);
    cudaGetSymbolAddress((void**)&p_ao, g_attnout);
    cudaGetSymbolAddress((void**)&p_qs, g_qs);
    cudaGetSymbolAddress((void**)&p_ks, g_ks);
    cudaGetSymbolAddress((void**)&p_uq, g_uq);
    cudaGetSymbolAddress((void**)&p_uk, g_uk);
    cudaGetSymbolAddress((void**)&p_c,  g_c);
    cudaGetSymbolAddress((void**)&p_part, g_part);
    cudaGetSymbolAddress((void**)&p_km, g_ksmax);

    cudaFuncSetAttribute(gemm_mma_kernel<0,128>, cudaFuncAttributeMaxDynamicSharedMemorySize, GEMM_SMEM);
    cudaFuncSetAttribute(gemm_mma_kernel<1,384>, cudaFuncAttributeMaxDynamicSharedMemorySize, GEMM_SMEM);
    cudaFuncSetAttribute(gemm_mma_kernel<2,256>, cudaFuncAttributeMaxDynamicSharedMemorySize, GEMM_SMEM);

    copy_ops_kernel<<<(BN*Dd)/256, 256>>>(ops, p_f0);
    begin_end_kernel<<<dim3(Bb,2), 128>>>(p_f0, begins, ends,
        init_bp_w, init_bp_b, init_ep_w, init_ep_b, p_f0);

    for (int l = 0; l < Ll; ++l) {
        float* cur = (l == 0) ? p_f0 : p_f1;
        float* nxt = (l == 0) ? p_f1 : p_f0;

        precompute_kernel<<<1, 128>>>(attn_w_w + (size_t)l*128*384, attn_w_b + (size_t)l*384,
                                      score_w + (size_t)l*256, score_b + l, p_uq, p_uk, p_c);
        qsks_kernel<<<BC/8, 256>>>(cur, p_uq, p_uk, p_c, p_qs, p_ks);
        ksmax_kernel<<<Bb, 256>>>(p_ks, p_km);

        gemm_mma_kernel<0,128><<<BC/128, 256, GEMM_SMEM>>>(cur, nullptr,
            attn_w_w + (size_t)l*128*384 + 256, 384, attn_w_b + (size_t)l*384 + 256,
            p_v, nullptr);

        begin_end_kernel<<<dim3(Bb,2), 128>>>(cur, begins, ends,
            be_bp_w + (size_t)l*128*128, be_bp_b + (size_t)l*128,
            be_ep_w + (size_t)l*128*128, be_ep_b + (size_t)l*128, p_seq);

        gemm_mma_kernel<1,384><<<BC/128, 256, GEMM_SMEM>>>(cur, nullptr,
            seq_mix_w + (size_t)l*384*128, 128, seq_mix_b + (size_t)l*128,
            p_seq, relations);

        attn_mma_kernel<<<dim3(Cc/128, Bb), 256>>>(p_v, p_qs, p_ks, p_km, mask, p_wt);

        gemm_mma_kernel<0,128><<<BC/128, 256, GEMM_SMEM>>>(p_wt, nullptr,
            attn_out_w + (size_t)l*128*128, 128, attn_out_b + (size_t)l*128,
            p_ao, nullptr);

        gemm_mma_kernel<2,256><<<BC/128, 256, GEMM_SMEM>>>(p_seq, p_ao,
            mix_w + (size_t)l*256*128, 128, mix_b + (size_t)l*128,
            nxt, nullptr);
    }

    mean1_kernel<<<dim3(Bb,16), 128>>>(p_f0, p_part);
    mean2_kernel<<<Bb, 128>>>(p_part, out);
    copyout_kernel<<<(BC*Dd)/256, 256>>>(p_f0, out + Bb*Dd);
}

// round 7
// speedup vs baseline: 2.2126x; 1.1729x over previous
#include <cuda_runtime.h>
#include <cuda_fp16.h>
#include <math.h>
#include <stdint.h>

#define Bb 8
#define Nn 2046
#define Dd 128
#define Jj 128
#define Ll 2
#define Cc 2048
#define BC (Bb*Cc)
#define BN (Bb*Nn)

__device__ float g_feats0[BC*Dd];
__device__ float g_feats1[BC*Dd];
__device__ float g_v[BC*Dd];
__device__ float g_seq[BC*Dd];
__device__ float g_weighted[BC*Dd];
__device__ float g_attnout[BC*Dd];
__device__ float g_qs[BC];
__device__ float g_ks[BC];
__device__ float g_uq[Dd];
__device__ float g_uk[Dd];
__device__ float g_c[2];
__device__ float g_part[Bb*16*Dd];
__device__ float g_ksmax[Bb];

// ---- fp16 split helpers ----
__device__ __forceinline__ uint32_t packsplit(float x, float y, uint32_t& lo){
    __half hx = __float2half_rn(x), hy = __float2half_rn(y);
    __half lx = __float2half_rn(x - __half2float(hx));
    __half ly = __float2half_rn(y - __half2float(hy));
    __half2 h = __halves2half2(hx, hy), l2 = __halves2half2(lx, ly);
    lo = *(uint32_t*)&l2;
    return *(uint32_t*)&h;
}
__device__ __forceinline__ void mma_f16(float c[4], const uint32_t a[4], uint32_t b0, uint32_t b1){
    asm volatile("mma.sync.aligned.m16n8k16.row.col.f32.f16.f16.f32 "
        "{%0,%1,%2,%3}, {%4,%5,%6,%7}, {%8,%9}, {%0,%1,%2,%3};"
        : "+f"(c[0]), "+f"(c[1]), "+f"(c[2]), "+f"(c[3])
        : "r"(a[0]), "r"(a[1]), "r"(a[2]), "r"(a[3]), "r"(b0), "r"(b1));
}

__global__ void copy_ops_kernel(const float* __restrict__ ops, float* __restrict__ feats){
    int idx = blockIdx.x * 256 + threadIdx.x;
    int b = idx / (Nn*Dd);
    int rem = idx - b*(Nn*Dd);
    feats[(size_t)b*Cc*Dd + rem] = ops[idx];
}
__global__ void copyout_kernel(const float* __restrict__ f, float* __restrict__ o){
    size_t i = (size_t)blockIdx.x * 256 + threadIdx.x; o[i] = f[i];
}

__global__ void __launch_bounds__(128) begin_end_kernel(
    const float* __restrict__ src, const int* __restrict__ bidx, const int* __restrict__ eidx,
    const float* __restrict__ Wb, const float* __restrict__ bb,
    const float* __restrict__ We, const float* __restrict__ be, float* __restrict__ dst){
    int b = blockIdx.x, which = blockIdx.y, tx = threadIdx.x;
    const int* idx = which ? eidx : bidx;
    const float* W = which ? We : Wb;
    const float* bias = which ? be : bb;
    __shared__ float avg[128];
    float s = 0.f;
    #pragma unroll 8
    for (int j = 0; j < Jj; ++j) s += src[((size_t)b*Cc + idx[b*Jj + j])*Dd + tx];
    avg[tx] = s * (1.f/Jj);
    __syncthreads();
    float o = 0.f;
    #pragma unroll 8
    for (int dd = 0; dd < Dd; ++dd) o += avg[dd] * W[dd*Dd + tx];
    dst[((size_t)b*Cc + Nn + which)*Dd + tx] = o + bias[tx];
}

__global__ void __launch_bounds__(128) precompute_kernel(
    const float* __restrict__ aw, const float* __restrict__ ab,
    const float* __restrict__ sw, const float* __restrict__ sb,
    float* __restrict__ uq, float* __restrict__ uk, float* __restrict__ cv){
    int d = threadIdx.x;
    float s1 = 0.f, s2 = 0.f;
    #pragma unroll 8
    for (int e = 0; e < 128; ++e) {
        s1 += aw[d*384 + e] * sw[e];
        s2 += aw[d*384 + 128 + e] * sw[128 + e];
    }
    uq[d] = s1; uk[d] = s2;
    if (d == 0) {
        float c1 = 0.f, c2 = 0.f;
        for (int e = 0; e < 128; ++e) { c1 += ab[e]*sw[e]; c2 += ab[128+e]*sw[128+e]; }
        cv[0] = c1; cv[1] = c2 + sb[0];
    }
}

__global__ void __launch_bounds__(256) qsks_kernel(
    const float* __restrict__ feats, const float* __restrict__ uq, const float* __restrict__ uk,
    const float* __restrict__ cv, float* __restrict__ qs, float* __restrict__ ks){
    int warp = threadIdx.x >> 5, lane = threadIdx.x & 31;
    int m = blockIdx.x * 8 + warp;
    float4 f = ((const float4*)(feats + (size_t)m*Dd))[lane];
    float4 q4 = ((const float4*)uq)[lane];
    float4 k4 = ((const float4*)uk)[lane];
    float dq = f.x*q4.x + f.y*q4.y + f.z*q4.z + f.w*q4.w;
    float dk = f.x*k4.x + f.y*k4.y + f.z*k4.z + f.w*k4.w;
    #pragma unroll
    for (int off = 16; off; off >>= 1) {
        dq += __shfl_down_sync(0xffffffffu, dq, off);
        dk += __shfl_down_sync(0xffffffffu, dk, off);
    }
    if (lane == 0) { qs[m] = dq + cv[0]; ks[m] = dk + cv[1]; }
}

__global__ void __launch_bounds__(256) ksmax_kernel(const float* __restrict__ ks, float* __restrict__ km){
    int b = blockIdx.x, tx = threadIdx.x;
    __shared__ float sm[256];
    float m = -1e30f;
    for (int j = tx; j < Cc; j += 256) m = fmaxf(m, ks[b*Cc + j]);
    sm[tx] = m; __syncthreads();
    for (int s = 128; s; s >>= 1) { if (tx < s) sm[tx] = fmaxf(sm[tx], sm[tx+s]); __syncthreads(); }
    if (tx == 0) km[b] = sm[0];
}

// ======== fp16 mma GEMM: 128 rows x 128 outs per block, 256 thr ========
#define PSTR 136
#define ASTRIDE 36

template<int MODE, int KTOT>
__global__ void __launch_bounds__(256) gemm_mma_kernel(
    const float* __restrict__ A, const float* __restrict__ A2,
    const float* __restrict__ W, int ws, const float* __restrict__ bias,
    float* __restrict__ out, const int* __restrict__ relations)
{
    __shared__ float As[128*ASTRIDE];
    __shared__ uint32_t Wph[16*PSTR];
    __shared__ uint32_t Wpl[16*PSTR];
    __shared__ int s_src[3][128];
    __shared__ int s_out[128];

    const int tid = threadIdx.x, w = tid>>5, lane = tid&31;
    const int g = lane>>2, l = lane&3;
    const int m0 = blockIdx.x * 128;

    if (tid < 128) {
        int m = m0 + tid;
        if (MODE == 1) {
            int b = m >> 11;
            int i = m & 2047;
            if (i < Nn) {
                s_src[0][tid] = b*Cc + i;
                int rp = relations[(size_t)(b*Nn + i)*2 + 0];
                int rs = relations[(size_t)(b*Nn + i)*2 + 1];
                s_src[1][tid] = b*Cc + (rp < 0 ? Nn : rp);
                s_src[2][tid] = b*Cc + (rs < 0 ? Nn + 1 : rs);
                s_out[tid] = m;
            } else {
                s_src[0][tid] = b*Cc; s_src[1][tid] = b*Cc; s_src[2][tid] = b*Cc;
                s_out[tid] = -1;
            }
        } else {
            s_out[tid] = m;
        }
    }

    float acc[16][4];
    #pragma unroll
    for (int nt = 0; nt < 16; ++nt) {
        acc[nt][0]=0.f; acc[nt][1]=0.f; acc[nt][2]=0.f; acc[nt][3]=0.f;
    }

    const int pr = tid>>4, cb = (tid&15)*8;   // W pair staging
    const int ar = tid>>1, ao = (tid&1)*16;   // A staging

    for (int k0 = 0; k0 < KTOT; k0 += 32) {
        __syncthreads();
        {   // stage W pair rows (k0+2pr, k0+2pr+1), 8 cols at cb
            const float* wa = W + (size_t)(k0 + 2*pr)*ws + cb;
            const float* wb = wa + ws;
            float4 a0 = *(const float4*)wa,    a1 = *(const float4*)(wa+4);
            float4 b0 = *(const float4*)wb,    b1 = *(const float4*)(wb+4);
            uint32_t* dh = Wph + pr*PSTR + cb;
            uint32_t* dl = Wpl + pr*PSTR + cb;
            uint32_t lo;
            dh[0] = packsplit(a0.x, b0.x, lo); dl[0] = lo;
            dh[1] = packsplit(a0.y, b0.y, lo); dl[1] = lo;
            dh[2] = packsplit(a0.z, b0.z, lo); dl[2] = lo;
            dh[3] = packsplit(a0.w, b0.w, lo); dl[3] = lo;
            dh[4] = packsplit(a1.x, b1.x, lo); dl[4] = lo;
            dh[5] = packsplit(a1.y, b1.y, lo); dl[5] = lo;
            dh[6] = packsplit(a1.z, b1.z, lo); dl[6] = lo;
            dh[7] = packsplit(a1.w, b1.w, lo); dl[7] = lo;
        }
        {   // stage A fp32 (row ar, 16 cols at ao)
            const float* asrc;
            if (MODE == 0) {
                asrc = A + (size_t)(m0 + ar)*128 + k0 + ao;
            } else if (MODE == 1) {
                int seg = k0 >> 7, col = k0 & 127;
                asrc = A + (size_t)s_src[seg][ar]*128 + col + ao;
            } else {
                int seg = k0 >> 7, col = k0 & 127;
                const float* base = seg ? A2 : A;
                asrc = base + (size_t)(m0 + ar)*128 + col + ao;
            }
            float* d = As + ar*ASTRIDE + ao;
            *(float4*)(d + 0)  = *(const float4*)(asrc + 0);
            *(float4*)(d + 4)  = *(const float4*)(asrc + 4);
            *(float4*)(d + 8)  = *(const float4*)(asrc + 8);
            *(float4*)(d + 12) = *(const float4*)(asrc + 12);
        }
        __syncthreads();

        #pragma unroll
        for (int kc = 0; kc < 2; ++kc) {
            const float* ap  = As + (16*w + g)*ASTRIDE + kc*16;
            const float* ap8 = ap + 8*ASTRIDE;
            float2 x0 = *(const float2*)(ap  + 2*l);
            float2 x1 = *(const float2*)(ap8 + 2*l);
            float2 x2 = *(const float2*)(ap  + 2*l + 8);
            float2 x3 = *(const float2*)(ap8 + 2*l + 8);
            uint32_t ah[4], al[4];
            ah[0] = packsplit(x0.x, x0.y, al[0]);
            ah[1] = packsplit(x1.x, x1.y, al[1]);
            ah[2] = packsplit(x2.x, x2.y, al[2]);
            ah[3] = packsplit(x3.x, x3.y, al[3]);
            const uint32_t* ph  = Wph + (kc*8 + l)*PSTR;
            const uint32_t* ph4 = Wph + (kc*8 + l + 4)*PSTR;
            const uint32_t* pl  = Wpl + (kc*8 + l)*PSTR;
            const uint32_t* pl4 = Wpl + (kc*8 + l + 4)*PSTR;
            #pragma unroll
            for (int nt = 0; nt < 16; ++nt) {
                int dcol = nt*8 + g;
                uint32_t bh0 = ph[dcol],  bh1 = ph4[dcol];
                uint32_t bl0 = pl[dcol],  bl1 = pl4[dcol];
                mma_f16(acc[nt], ah, bh0, bh1);
                mma_f16(acc[nt], al, bh0, bh1);
                mma_f16(acc[nt], ah, bl0, bl1);
            }
        }
    }

    const int r0 = 16*w + g;
    const int o0 = s_out[r0], o1 = s_out[r0 + 8];
    float* w0 = out + (size_t)o0*128;
    float* w1 = out + (size_t)o1*128;
    #pragma unroll
    for (int nt = 0; nt < 16; ++nt) {
        int col = nt*8 + 2*l;
        float b0 = __ldg(bias + col), b1 = __ldg(bias + col + 1);
        if (o0 >= 0) *(float2*)(w0 + col) = make_float2(acc[nt][0]+b0, acc[nt][1]+b1);
        if (o1 >= 0) *(float2*)(w1 + col) = make_float2(acc[nt][2]+b0, acc[nt][3]+b1);
    }
}

// ======== fp16 mma attention: grid(16,B), 256 thr ========
__device__ __forceinline__ float pval(float q, float M, float kv, float mv){
    float x = q + kv; x = x > 0.f ? x : 0.01f*x;
    return __expf(x*mv - M);
}
__device__ __forceinline__ float mval(const float* mrow, bool in, int gi, int j){
    return (in && j < Nn) ? __ldg(mrow + j) : ((gi == j) ? 1.f : 0.f);
}

__global__ void __launch_bounds__(256) attn_mma_kernel(
    const float* __restrict__ v, const float* __restrict__ qs,
    const float* __restrict__ ks, const float* __restrict__ ksmax,
    const float* __restrict__ mask, float* __restrict__ weighted)
{
    __shared__ uint32_t Vph[16*PSTR];
    __shared__ uint32_t Vpl[16*PSTR];
    __shared__ float s_ks[32];

    const int b = blockIdx.y, i0 = blockIdx.x*128;
    const int tid = threadIdx.x, w = tid>>5, lane = tid&31;
    const int g = lane>>2, l = lane&3;
    const int r0 = 16*w + g, r1 = r0 + 8;
    const int gi0 = i0 + r0, gi1 = i0 + r1;

    const float q0 = qs[b*Cc + gi0];
    const float q1 = qs[b*Cc + gi1];
    const float km = ksmax[b];
    float t0 = q0 + km; t0 = t0 > 0.f ? t0 : 0.01f*t0;
    float t1 = q1 + km; t1 = t1 > 0.f ? t1 : 0.01f*t1;
    const float M0 = fmaxf(0.f, t0);
    const float M1 = fmaxf(0.f, t1);
    float sum0 = 0.f, sum1 = 0.f;

    const float* mrow0 = mask + (size_t)b*Nn*Nn + (size_t)gi0*Nn;
    const float* mrow1 = mask + (size_t)b*Nn*Nn + (size_t)gi1*Nn;
    const bool in0 = gi0 < Nn, in1 = gi1 < Nn;

    float acc[16][4];
    #pragma unroll
    for (int nt = 0; nt < 16; ++nt) {
        acc[nt][0]=0.f; acc[nt][1]=0.f; acc[nt][2]=0.f; acc[nt][3]=0.f;
    }

    const int pr = tid>>4, cb = (tid&15)*8;

    for (int j0 = 0; j0 < Cc; j0 += 32) {
        __syncthreads();
        {   // stage V pair rows (j0+2pr, j0+2pr+1), 8 cols at cb
            const float* va = v + ((size_t)(b*Cc + j0 + 2*pr))*128 + cb;
            const float* vb = va + 128;
            float4 a0 = *(const float4*)va,  a1 = *(const float4*)(va+4);
            float4 b0 = *(const float4*)vb,  b1 = *(const float4*)(vb+4);
            uint32_t* dh = Vph + pr*PSTR + cb;
            uint32_t* dl = Vpl + pr*PSTR + cb;
            uint32_t lo;
            dh[0] = packsplit(a0.x, b0.x, lo); dl[0] = lo;
            dh[1] = packsplit(a0.y, b0.y, lo); dl[1] = lo;
            dh[2] = packsplit(a0.z, b0.z, lo); dl[2] = lo;
            dh[3] = packsplit(a0.w, b0.w, lo); dl[3] = lo;
            dh[4] = packsplit(a1.x, b1.x, lo); dl[4] = lo;
            dh[5] = packsplit(a1.y, b1.y, lo); dl[5] = lo;
            dh[6] = packsplit(a1.z, b1.z, lo); dl[6] = lo;
            dh[7] = packsplit(a1.w, b1.w, lo); dl[7] = lo;
            if (tid < 32) s_ks[tid] = ks[b*Cc + j0 + tid];
        }
        __syncthreads();

        #pragma unroll
        for (int kc = 0; kc < 2; ++kc) {
            const int kb = kc*16 + 2*l;
            const int ja = j0 + kb;
            const float kv0 = s_ks[kb],   kv1 = s_ks[kb+1];
            const float kv8 = s_ks[kb+8], kv9 = s_ks[kb+9];
            float m00 = mval(mrow0, in0, gi0, ja);
            float m01 = mval(mrow0, in0, gi0, ja+1);
            float m08 = mval(mrow0, in0, gi0, ja+8);
            float m09 = mval(mrow0, in0, gi0, ja+9);
            float m10 = mval(mrow1, in1, gi1, ja);
            float m11 = mval(mrow1, in1, gi1, ja+1);
            float m18 = mval(mrow1, in1, gi1, ja+8);
            float m19 = mval(mrow1, in1, gi1, ja+9);
            float p00 = pval(q0, M0, kv0, m00);
            float p01 = pval(q0, M0, kv1, m01);
            float p08 = pval(q0, M0, kv8, m08);
            float p09 = pval(q0, M0, kv9, m09);
            float p10 = pval(q1, M1, kv0, m10);
            float p11 = pval(q1, M1, kv1, m11);
            float p18 = pval(q1, M1, kv8, m18);
            float p19 = pval(q1, M1, kv9, m19);
            sum0 += p00 + p01 + p08 + p09;
            sum1 += p10 + p11 + p18 + p19;
            uint32_t ah[4], al[4];
            ah[0] = packsplit(p00, p01, al[0]);
            ah[1] = packsplit(p10, p11, al[1]);
            ah[2] = packsplit(p08, p09, al[2]);
            ah[3] = packsplit(p18, p19, al[3]);
            const uint32_t* ph  = Vph + (kc*8 + l)*PSTR;
            const uint32_t* ph4 = Vph + (kc*8 + l + 4)*PSTR;
            const uint32_t* pl  = Vpl + (kc*8 + l)*PSTR;
            const uint32_t* pl4 = Vpl + (kc*8 + l + 4)*PSTR;
            #pragma unroll
            for (int nt = 0; nt < 16; ++nt) {
                int dcol = nt*8 + g;
                uint32_t bh0 = ph[dcol],  bh1 = ph4[dcol];
                uint32_t bl0 = pl[dcol],  bl1 = pl4[dcol];
                mma_f16(acc[nt], ah, bh0, bh1);
                mma_f16(acc[nt], al, bh0, bh1);
                mma_f16(acc[nt], ah, bl0, bl1);
            }
        }
    }

    sum0 += __shfl_xor_sync(0xffffffffu, sum0, 1);
    sum0 += __shfl_xor_sync(0xffffffffu, sum0, 2);
    sum1 += __shfl_xor_sync(0xffffffffu, sum1, 1);
    sum1 += __shfl_xor_sync(0xffffffffu, sum1, 2);
    float inv0 = 1.f / sum0, inv1 = 1.f / sum1;

    float* w0 = weighted + ((size_t)(b*Cc + gi0))*128;
    float* w1 = weighted + ((size_t)(b*Cc + gi1))*128;
    #pragma unroll
    for (int nt = 0; nt < 16; ++nt) {
        int col = nt*8 + 2*l;
        *(float2*)(w0 + col) = make_float2(acc[nt][0]*inv0, acc[nt][1]*inv0);
        *(float2*)(w1 + col) = make_float2(acc[nt][2]*inv1, acc[nt][3]*inv1);
    }
}

// exact fp32 recompute of attention rows N, N+1 (diag-only mask)
__global__ void __launch_bounds__(128) fixup_kernel(
    const float* __restrict__ v, const float* __restrict__ part,
    const float* __restrict__ qs, const float* __restrict__ ks,
    float* __restrict__ weighted)
{
    int b = blockIdx.x, which = blockIdx.y, tx = threadIdx.x;
    int r = Nn + which;
    float vsum = 0.f;
    #pragma unroll
    for (int p = 0; p < 16; ++p) vsum += part[(b*16 + p)*128 + tx];
    float s = qs[b*Cc + r] + ks[b*Cc + r];
    s = s > 0.f ? s : 0.01f*s;
    float mx = fmaxf(s, 0.f);
    float es = __expf(s - mx), e0 = __expf(-mx);
    float vr = v[((size_t)(b*Cc + r))*128 + tx];
    float denom = es + (float)(Cc - 1) * e0;
    weighted[((size_t)(b*Cc + r))*128 + tx] = (es*vr + e0*(vsum - vr)) / denom;
}

__global__ void __launch_bounds__(128) mean1_kernel(const float* __restrict__ f, float* __restrict__ part){
    int b = blockIdx.x, p = blockIdx.y, tx = threadIdx.x;
    float s = 0.f;
    #pragma unroll 8
    for (int i = 0; i < Cc/16; ++i) s += f[((size_t)b*Cc + p*(Cc/16) + i)*128 + tx];
    part[(b*16 + p)*128 + tx] = s;
}
__global__ void __launch_bounds__(128) mean2_kernel(const float* __restrict__ part, float* __restrict__ out){
    int b = blockIdx.x, tx = threadIdx.x;
    float s = 0.f;
    #pragma unroll
    for (int p = 0; p < 16; ++p) s += part[(b*16 + p)*128 + tx];
    out[b*128 + tx] = s * (1.f/Cc);
}

extern "C" void kernel_launch(void* const* d_in, const int* in_sizes, int n_in,
                              void* d_out, int out_size)
{
    const float* ops       = (const float*)d_in[0];
    const float* mask      = (const float*)d_in[1];
    const int*   relations = (const int*)d_in[2];
    const int*   begins    = (const int*)d_in[3];
    const int*   ends      = (const int*)d_in[4];
    const float* init_bp_w = (const float*)d_in[5];
    const float* init_bp_b = (const float*)d_in[6];
    const float* init_ep_w = (const float*)d_in[7];
    const float* init_ep_b = (const float*)d_in[8];
    const float* be_bp_w   = (const float*)d_in[9];
    const float* be_bp_b   = (const float*)d_in[10];
    const float* be_ep_w   = (const float*)d_in[11];
    const float* be_ep_b   = (const float*)d_in[12];
    const float* seq_mix_w = (const float*)d_in[13];
    const float* seq_mix_b = (const float*)d_in[14];
    const float* attn_w_w  = (const float*)d_in[15];
    const float* attn_w_b  = (const float*)d_in[16];
    const float* score_w   = (const float*)d_in[17];
    const float* score_b   = (const float*)d_in[18];
    const float* attn_out_w= (const float*)d_in[19];
    const float* attn_out_b= (const float*)d_in[20];
    const float* mix_w     = (const float*)d_in[21];
    const float* mix_b     = (const float*)d_in[22];
    float* out = (float*)d_out;

    float *p_f0,*p_f1,*p_v,*p_seq,*p_wt,*p_ao,*p_qs,*p_ks,*p_uq,*p_uk,*p_c,*p_part,*p_km;
    cudaGetSymbolAddress((void**)&p_f0, g_feats0);
    cudaGetSymbolAddress((void**)&p_f1, g_feats1);
    cudaGetSymbolAddress((void**)&p_v,  g_v);
    cudaGetSymbolAddress((void**)&p_seq, g_seq);
    cudaGetSymbolAddress((void**)&p_wt, g_weighted);
    cudaGetSymbolAddress((void**)&p_ao, g_attnout);
    cudaGetSymbolAddress((void**)&p_qs, g_qs);
    cudaGetSymbolAddress((void**)&p_ks, g_ks);
    cudaGetSymbolAddress((void**)&p_uq, g_uq);
    cudaGetSymbolAddress((void**)&p_uk, g_uk);
    cudaGetSymbolAddress((void**)&p_c,  g_c);
    cudaGetSymbolAddress((void**)&p_part, g_part);
    cudaGetSymbolAddress((void**)&p_km, g_ksmax);

    copy_ops_kernel<<<(BN*Dd)/256, 256>>>(ops, p_f0);
    begin_end_kernel<<<dim3(Bb,2), 128>>>(p_f0, begins, ends,
        init_bp_w, init_bp_b, init_ep_w, init_ep_b, p_f0);

    for (int l = 0; l < Ll; ++l) {
        float* cur = (l == 0) ? p_f0 : p_f1;
        float* nxt = (l == 0) ? p_f1 : p_f0;

        precompute_kernel<<<1, 128>>>(attn_w_w + (size_t)l*128*384, attn_w_b + (size_t)l*384,
                                      score_w + (size_t)l*256, score_b + l, p_uq, p_uk, p_c);
        qsks_kernel<<<BC/8, 256>>>(cur, p_uq, p_uk, p_c, p_qs, p_ks);
        ksmax_kernel<<<Bb, 256>>>(p_ks, p_km);

        gemm_mma_kernel<0,128><<<BC/128, 256>>>(cur, nullptr,
            attn_w_w + (size_t)l*128*384 + 256, 384, attn_w_b + (size_t)l*384 + 256,
            p_v, nullptr);
        mean1_kernel<<<dim3(Bb,16), 128>>>(p_v, p_part);   // V column partial sums

        begin_end_kernel<<<dim3(Bb,2), 128>>>(cur, begins, ends,
            be_bp_w + (size_t)l*128*128, be_bp_b + (size_t)l*128,
            be_ep_w + (size_t)l*128*128, be_ep_b + (size_t)l*128, p_seq);

        gemm_mma_kernel<1,384><<<BC/128, 256>>>(cur, nullptr,
            seq_mix_w + (size_t)l*384*128, 128, seq_mix_b + (size_t)l*128,
            p_seq, relations);

        attn_mma_kernel<<<dim3(Cc/128, Bb), 256>>>(p_v, p_qs, p_ks, p_km, mask, p_wt);
        fixup_kernel<<<dim3(Bb,2), 128>>>(p_v, p_part, p_qs, p_ks, p_wt);

        gemm_mma_kernel<0,128><<<BC/128, 256>>>(p_wt, nullptr,
            attn_out_w + (size_t)l*128*128, 128, attn_out_b + (size_t)l*128,
            p_ao, nullptr);

        gemm_mma_kernel<2,256><<<BC/128, 256>>>(p_seq, p_ao,
            mix_w + (size_t)l*256*128, 128, mix_b + (size_t)l*128,
            nxt, nullptr);
    }

    mean1_kernel<<<dim3(Bb,16), 128>>>(p_f0, p_part);
    mean2_kernel<<<Bb, 128>>>(p_part, out);
    copyout_kernel<<<(BC*Dd)/256, 256>>>(p_f0, out + Bb*Dd);
}

// round 8
// speedup vs baseline: 2.6488x; 1.1971x over previous
#include <cuda_runtime.h>
#include <cuda_fp16.h>
#include <math.h>
#include <stdint.h>

#define Bb 8
#define Nn 2046
#define Dd 128
#define Jj 128
#define Ll 2
#define Cc 2048
#define BC (Bb*Cc)
#define BN (Bb*Nn)

__device__ float g_feats0[BC*Dd];
__device__ float g_feats1[BC*Dd];
__device__ float g_v[BC*Dd];
__device__ float g_seq[BC*Dd];
__device__ float g_weighted[BC*Dd];
__device__ float g_attnout[BC*Dd];
__device__ float g_num[2*BC*Dd];
__device__ float g_den[2*BC];
__device__ float g_qs[BC];
__device__ float g_ks[BC];
__device__ float g_uq[Dd];
__device__ float g_uk[Dd];
__device__ float g_c[2];
__device__ float g_part[Bb*16*Dd];
__device__ float g_ksmax[Bb];

// ---- fp16 split helpers ----
__device__ __forceinline__ uint32_t packsplit(float x, float y, uint32_t& lo){
    __half hx = __float2half_rn(x), hy = __float2half_rn(y);
    __half lx = __float2half_rn(x - __half2float(hx));
    __half ly = __float2half_rn(y - __half2float(hy));
    __half2 h = __halves2half2(hx, hy), l2 = __halves2half2(lx, ly);
    lo = *(uint32_t*)&l2;
    return *(uint32_t*)&h;
}
__device__ __forceinline__ void mma_f16(float c[4], const uint32_t a[4], uint32_t b0, uint32_t b1){
    asm volatile("mma.sync.aligned.m16n8k16.row.col.f32.f16.f16.f32 "
        "{%0,%1,%2,%3}, {%4,%5,%6,%7}, {%8,%9}, {%0,%1,%2,%3};"
        : "+f"(c[0]), "+f"(c[1]), "+f"(c[2]), "+f"(c[3])
        : "r"(a[0]), "r"(a[1]), "r"(a[2]), "r"(a[3]), "r"(b0), "r"(b1));
}

__global__ void copy_ops_kernel(const float* __restrict__ ops, float* __restrict__ feats){
    int idx = blockIdx.x * 256 + threadIdx.x;
    int b = idx / (Nn*Dd);
    int rem = idx - b*(Nn*Dd);
    feats[(size_t)b*Cc*Dd + rem] = ops[idx];
}
__global__ void copyout_kernel(const float* __restrict__ f, float* __restrict__ o){
    size_t i = (size_t)blockIdx.x * 256 + threadIdx.x; o[i] = f[i];
}

__global__ void __launch_bounds__(128) begin_end_kernel(
    const float* __restrict__ src, const int* __restrict__ bidx, const int* __restrict__ eidx,
    const float* __restrict__ Wb, const float* __restrict__ bb,
    const float* __restrict__ We, const float* __restrict__ be, float* __restrict__ dst){
    int b = blockIdx.x, which = blockIdx.y, tx = threadIdx.x;
    const int* idx = which ? eidx : bidx;
    const float* W = which ? We : Wb;
    const float* bias = which ? be : bb;
    __shared__ float avg[128];
    float s = 0.f;
    #pragma unroll 8
    for (int j = 0; j < Jj; ++j) s += src[((size_t)b*Cc + idx[b*Jj + j])*Dd + tx];
    avg[tx] = s * (1.f/Jj);
    __syncthreads();
    float o = 0.f;
    #pragma unroll 8
    for (int dd = 0; dd < Dd; ++dd) o += avg[dd] * W[dd*Dd + tx];
    dst[((size_t)b*Cc + Nn + which)*Dd + tx] = o + bias[tx];
}

__global__ void __launch_bounds__(128) precompute_kernel(
    const float* __restrict__ aw, const float* __restrict__ ab,
    const float* __restrict__ sw, const float* __restrict__ sb,
    float* __restrict__ uq, float* __restrict__ uk, float* __restrict__ cv){
    int d = threadIdx.x;
    float s1 = 0.f, s2 = 0.f;
    #pragma unroll 8
    for (int e = 0; e < 128; ++e) {
        s1 += aw[d*384 + e] * sw[e];
        s2 += aw[d*384 + 128 + e] * sw[128 + e];
    }
    uq[d] = s1; uk[d] = s2;
    if (d == 0) {
        float c1 = 0.f, c2 = 0.f;
        for (int e = 0; e < 128; ++e) { c1 += ab[e]*sw[e]; c2 += ab[128+e]*sw[128+e]; }
        cv[0] = c1; cv[1] = c2 + sb[0];
    }
}

__global__ void __launch_bounds__(256) qsks_kernel(
    const float* __restrict__ feats, const float* __restrict__ uq, const float* __restrict__ uk,
    const float* __restrict__ cv, float* __restrict__ qs, float* __restrict__ ks){
    int warp = threadIdx.x >> 5, lane = threadIdx.x & 31;
    int m = blockIdx.x * 8 + warp;
    float4 f = ((const float4*)(feats + (size_t)m*Dd))[lane];
    float4 q4 = ((const float4*)uq)[lane];
    float4 k4 = ((const float4*)uk)[lane];
    float dq = f.x*q4.x + f.y*q4.y + f.z*q4.z + f.w*q4.w;
    float dk = f.x*k4.x + f.y*k4.y + f.z*k4.z + f.w*k4.w;
    #pragma unroll
    for (int off = 16; off; off >>= 1) {
        dq += __shfl_down_sync(0xffffffffu, dq, off);
        dk += __shfl_down_sync(0xffffffffu, dk, off);
    }
    if (lane == 0) { qs[m] = dq + cv[0]; ks[m] = dk + cv[1]; }
}

__global__ void __launch_bounds__(256) ksmax_kernel(const float* __restrict__ ks, float* __restrict__ km){
    int b = blockIdx.x, tx = threadIdx.x;
    __shared__ float sm[256];
    float m = -1e30f;
    for (int j = tx; j < Cc; j += 256) m = fmaxf(m, ks[b*Cc + j]);
    sm[tx] = m; __syncthreads();
    for (int s = 128; s; s >>= 1) { if (tx < s) sm[tx] = fmaxf(sm[tx], sm[tx+s]); __syncthreads(); }
    if (tx == 0) km[b] = sm[0];
}

// ======== fp16 mma GEMM: 128 rows x 64 outs per block (col-split x2), 256 thr ========
#define PST2 72
#define ASTRIDE 36

template<int MODE, int KTOT>
__global__ void __launch_bounds__(256) gemm_mma_kernel(
    const float* __restrict__ A, const float* __restrict__ A2,
    const float* __restrict__ W, int ws, const float* __restrict__ bias,
    float* __restrict__ out, const int* __restrict__ relations)
{
    __shared__ float As[128*ASTRIDE];
    __shared__ uint32_t Wph[16*PST2];
    __shared__ uint32_t Wpl[16*PST2];
    __shared__ int s_src[3][128];
    __shared__ int s_out[128];

    const int tid = threadIdx.x, w = tid>>5, lane = tid&31;
    const int g = lane>>2, l = lane&3;
    const int m0 = blockIdx.x * 128;
    const int ch = blockIdx.y;          // column half: cols [64*ch, 64*ch+64)
    const int c0 = ch * 64;

    if (tid < 128) {
        int m = m0 + tid;
        if (MODE == 1) {
            int b = m >> 11;
            int i = m & 2047;
            if (i < Nn) {
                s_src[0][tid] = b*Cc + i;
                int rp = relations[(size_t)(b*Nn + i)*2 + 0];
                int rs = relations[(size_t)(b*Nn + i)*2 + 1];
                s_src[1][tid] = b*Cc + (rp < 0 ? Nn : rp);
                s_src[2][tid] = b*Cc + (rs < 0 ? Nn + 1 : rs);
                s_out[tid] = m;
            } else {
                s_src[0][tid] = b*Cc; s_src[1][tid] = b*Cc; s_src[2][tid] = b*Cc;
                s_out[tid] = -1;
            }
        } else {
            s_out[tid] = m;
        }
    }

    float acc[8][4];
    #pragma unroll
    for (int nt = 0; nt < 8; ++nt) {
        acc[nt][0]=0.f; acc[nt][1]=0.f; acc[nt][2]=0.f; acc[nt][3]=0.f;
    }

    const int pr = tid>>4, cb4 = (tid&15)*4;  // W pair staging: 4 cols/thread
    const int ar = tid>>1, ao = (tid&1)*16;   // A staging

    for (int k0 = 0; k0 < KTOT; k0 += 32) {
        __syncthreads();
        {   // stage W pair rows (k0+2pr, k0+2pr+1), 4 cols at c0+cb4
            const float* wa = W + (size_t)(k0 + 2*pr)*ws + c0 + cb4;
            const float* wb = wa + ws;
            float4 a0 = *(const float4*)wa;
            float4 b0 = *(const float4*)wb;
            uint32_t* dh = Wph + pr*PST2 + cb4;
            uint32_t* dl = Wpl + pr*PST2 + cb4;
            uint32_t lo;
            dh[0] = packsplit(a0.x, b0.x, lo); dl[0] = lo;
            dh[1] = packsplit(a0.y, b0.y, lo); dl[1] = lo;
            dh[2] = packsplit(a0.z, b0.z, lo); dl[2] = lo;
            dh[3] = packsplit(a0.w, b0.w, lo); dl[3] = lo;
        }
        {   // stage A fp32 (row ar, 16 cols at ao)
            const float* asrc;
            if (MODE == 0) {
                asrc = A + (size_t)(m0 + ar)*128 + k0 + ao;
            } else if (MODE == 1) {
                int seg = k0 >> 7, col = k0 & 127;
                asrc = A + (size_t)s_src[seg][ar]*128 + col + ao;
            } else {
                int seg = k0 >> 7, col = k0 & 127;
                const float* base = seg ? A2 : A;
                asrc = base + (size_t)(m0 + ar)*128 + col + ao;
            }
            float* d = As + ar*ASTRIDE + ao;
            *(float4*)(d + 0)  = *(const float4*)(asrc + 0);
            *(float4*)(d + 4)  = *(const float4*)(asrc + 4);
            *(float4*)(d + 8)  = *(const float4*)(asrc + 8);
            *(float4*)(d + 12) = *(const float4*)(asrc + 12);
        }
        __syncthreads();

        #pragma unroll
        for (int kc = 0; kc < 2; ++kc) {
            const float* ap  = As + (16*w + g)*ASTRIDE + kc*16;
            const float* ap8 = ap + 8*ASTRIDE;
            float2 x0 = *(const float2*)(ap  + 2*l);
            float2 x1 = *(const float2*)(ap8 + 2*l);
            float2 x2 = *(const float2*)(ap  + 2*l + 8);
            float2 x3 = *(const float2*)(ap8 + 2*l + 8);
            uint32_t ah[4], al[4];
            ah[0] = packsplit(x0.x, x0.y, al[0]);
            ah[1] = packsplit(x1.x, x1.y, al[1]);
            ah[2] = packsplit(x2.x, x2.y, al[2]);
            ah[3] = packsplit(x3.x, x3.y, al[3]);
            const uint32_t* ph  = Wph + (kc*8 + l)*PST2;
            const uint32_t* ph4 = Wph + (kc*8 + l + 4)*PST2;
            const uint32_t* pl  = Wpl + (kc*8 + l)*PST2;
            const uint32_t* pl4 = Wpl + (kc*8 + l + 4)*PST2;
            #pragma unroll
            for (int nt = 0; nt < 8; ++nt) {
                int dcol = nt*8 + g;
                uint32_t bh0 = ph[dcol],  bh1 = ph4[dcol];
                uint32_t bl0 = pl[dcol],  bl1 = pl4[dcol];
                mma_f16(acc[nt], ah, bh0, bh1);
                mma_f16(acc[nt], al, bh0, bh1);
                mma_f16(acc[nt], ah, bl0, bl1);
            }
        }
    }

    const int r0 = 16*w + g;
    const int o0 = s_out[r0], o1 = s_out[r0 + 8];
    float* w0 = out + (size_t)o0*128;
    float* w1 = out + (size_t)o1*128;
    #pragma unroll
    for (int nt = 0; nt < 8; ++nt) {
        int col = c0 + nt*8 + 2*l;
        float b0 = __ldg(bias + col), b1 = __ldg(bias + col + 1);
        if (o0 >= 0) *(float2*)(w0 + col) = make_float2(acc[nt][0]+b0, acc[nt][1]+b1);
        if (o1 >= 0) *(float2*)(w1 + col) = make_float2(acc[nt][2]+b0, acc[nt][3]+b1);
    }
}

// ======== fp16 mma attention, j-split x2: grid(32,B), 256 thr ========
#define PSTR 136
__device__ __forceinline__ float pval(float q, float M, float kv, float mv){
    float x = q + kv; x = x > 0.f ? x : 0.01f*x;
    return __expf(x*mv - M);
}
__device__ __forceinline__ float mval(const float* mrow, bool in, int gi, int j){
    return (in && j < Nn) ? __ldg(mrow + j) : ((gi == j) ? 1.f : 0.f);
}

__global__ void __launch_bounds__(256) attn_mma_kernel(
    const float* __restrict__ v, const float* __restrict__ qs,
    const float* __restrict__ ks, const float* __restrict__ ksmax,
    const float* __restrict__ mask, float* __restrict__ num, float* __restrict__ den)
{
    __shared__ uint32_t Vph[16*PSTR];
    __shared__ uint32_t Vpl[16*PSTR];
    __shared__ float s_ks[32];

    const int b = blockIdx.y;
    const int jc = blockIdx.x & 1;
    const int i0 = (blockIdx.x >> 1) * 128;
    const int tid = threadIdx.x, w = tid>>5, lane = tid&31;
    const int g = lane>>2, l = lane&3;
    const int r0 = 16*w + g, r1 = r0 + 8;
    const int gi0 = i0 + r0, gi1 = i0 + r1;

    const float q0 = qs[b*Cc + gi0];
    const float q1 = qs[b*Cc + gi1];
    const float km = ksmax[b];
    float t0 = q0 + km; t0 = t0 > 0.f ? t0 : 0.01f*t0;
    float t1 = q1 + km; t1 = t1 > 0.f ? t1 : 0.01f*t1;
    const float M0 = fmaxf(0.f, t0);
    const float M1 = fmaxf(0.f, t1);
    float sum0 = 0.f, sum1 = 0.f;

    const float* mrow0 = mask + (size_t)b*Nn*Nn + (size_t)gi0*Nn;
    const float* mrow1 = mask + (size_t)b*Nn*Nn + (size_t)gi1*Nn;
    const bool in0 = gi0 < Nn, in1 = gi1 < Nn;

    float acc[16][4];
    #pragma unroll
    for (int nt = 0; nt < 16; ++nt) {
        acc[nt][0]=0.f; acc[nt][1]=0.f; acc[nt][2]=0.f; acc[nt][3]=0.f;
    }

    const int pr = tid>>4, cb = (tid&15)*8;
    const int jbeg = jc * 1024, jend = jbeg + 1024;

    for (int j0 = jbeg; j0 < jend; j0 += 32) {
        __syncthreads();
        {   // stage V pair rows (j0+2pr, j0+2pr+1), 8 cols at cb
            const float* va = v + ((size_t)(b*Cc + j0 + 2*pr))*128 + cb;
            const float* vb = va + 128;
            float4 a0 = *(const float4*)va,  a1 = *(const float4*)(va+4);
            float4 b0 = *(const float4*)vb,  b1 = *(const float4*)(vb+4);
            uint32_t* dh = Vph + pr*PSTR + cb;
            uint32_t* dl = Vpl + pr*PSTR + cb;
            uint32_t lo;
            dh[0] = packsplit(a0.x, b0.x, lo); dl[0] = lo;
            dh[1] = packsplit(a0.y, b0.y, lo); dl[1] = lo;
            dh[2] = packsplit(a0.z, b0.z, lo); dl[2] = lo;
            dh[3] = packsplit(a0.w, b0.w, lo); dl[3] = lo;
            dh[4] = packsplit(a1.x, b1.x, lo); dl[4] = lo;
            dh[5] = packsplit(a1.y, b1.y, lo); dl[5] = lo;
            dh[6] = packsplit(a1.z, b1.z, lo); dl[6] = lo;
            dh[7] = packsplit(a1.w, b1.w, lo); dl[7] = lo;
            if (tid < 32) s_ks[tid] = ks[b*Cc + j0 + tid];
        }
        __syncthreads();

        // hoisted mask loads for both kc halves (MLP=16)
        float m0v[8], m1v[8];
        #pragma unroll
        for (int kc = 0; kc < 2; ++kc) {
            int ja = j0 + kc*16 + 2*l;
            m0v[kc*4+0] = mval(mrow0, in0, gi0, ja);
            m0v[kc*4+1] = mval(mrow0, in0, gi0, ja+1);
            m0v[kc*4+2] = mval(mrow0, in0, gi0, ja+8);
            m0v[kc*4+3] = mval(mrow0, in0, gi0, ja+9);
            m1v[kc*4+0] = mval(mrow1, in1, gi1, ja);
            m1v[kc*4+1] = mval(mrow1, in1, gi1, ja+1);
            m1v[kc*4+2] = mval(mrow1, in1, gi1, ja+8);
            m1v[kc*4+3] = mval(mrow1, in1, gi1, ja+9);
        }

        #pragma unroll
        for (int kc = 0; kc < 2; ++kc) {
            const int kb = kc*16 + 2*l;
            const float kv0 = s_ks[kb],   kv1 = s_ks[kb+1];
            const float kv8 = s_ks[kb+8], kv9 = s_ks[kb+9];
            float p00 = pval(q0, M0, kv0, m0v[kc*4+0]);
            float p01 = pval(q0, M0, kv1, m0v[kc*4+1]);
            float p08 = pval(q0, M0, kv8, m0v[kc*4+2]);
            float p09 = pval(q0, M0, kv9, m0v[kc*4+3]);
            float p10 = pval(q1, M1, kv0, m1v[kc*4+0]);
            float p11 = pval(q1, M1, kv1, m1v[kc*4+1]);
            float p18 = pval(q1, M1, kv8, m1v[kc*4+2]);
            float p19 = pval(q1, M1, kv9, m1v[kc*4+3]);
            sum0 += p00 + p01 + p08 + p09;
            sum1 += p10 + p11 + p18 + p19;
            uint32_t ah[4], al[4];
            ah[0] = packsplit(p00, p01, al[0]);
            ah[1] = packsplit(p10, p11, al[1]);
            ah[2] = packsplit(p08, p09, al[2]);
            ah[3] = packsplit(p18, p19, al[3]);
            const uint32_t* ph  = Vph + (kc*8 + l)*PSTR;
            const uint32_t* ph4 = Vph + (kc*8 + l + 4)*PSTR;
            const uint32_t* pl  = Vpl + (kc*8 + l)*PSTR;
            const uint32_t* pl4 = Vpl + (kc*8 + l + 4)*PSTR;
            #pragma unroll
            for (int nt = 0; nt < 16; ++nt) {
                int dcol = nt*8 + g;
                uint32_t bh0 = ph[dcol],  bh1 = ph4[dcol];
                uint32_t bl0 = pl[dcol],  bl1 = pl4[dcol];
                mma_f16(acc[nt], ah, bh0, bh1);
                mma_f16(acc[nt], al, bh0, bh1);
                mma_f16(acc[nt], ah, bl0, bl1);
            }
        }
    }

    sum0 += __shfl_xor_sync(0xffffffffu, sum0, 1);
    sum0 += __shfl_xor_sync(0xffffffffu, sum0, 2);
    sum1 += __shfl_xor_sync(0xffffffffu, sum1, 1);
    sum1 += __shfl_xor_sync(0xffffffffu, sum1, 2);
    if (l == 0) {
        den[(size_t)jc*BC + b*Cc + gi0] = sum0;
        den[(size_t)jc*BC + b*Cc + gi1] = sum1;
    }

    float* n0 = num + (size_t)jc*BC*Dd + ((size_t)(b*Cc + gi0))*128;
    float* n1 = num + (size_t)jc*BC*Dd + ((size_t)(b*Cc + gi1))*128;
    #pragma unroll
    for (int nt = 0; nt < 16; ++nt) {
        int col = nt*8 + 2*l;
        *(float2*)(n0 + col) = make_float2(acc[nt][0], acc[nt][1]);
        *(float2*)(n1 + col) = make_float2(acc[nt][2], acc[nt][3]);
    }
}

// combine j-split partials: wt = (num0+num1)/(den0+den1)
__global__ void __launch_bounds__(256) combine_kernel(
    const float* __restrict__ num, const float* __restrict__ den,
    float* __restrict__ wt)
{
    size_t idx = (size_t)blockIdx.x*256 + threadIdx.x;   // BC*Dd / 256
    int m = (int)(idx >> 7);
    float d = den[m] + den[BC + m];
    wt[idx] = (num[idx] + num[(size_t)BC*Dd + idx]) / d;
}

// exact fp32 recompute of attention rows N, N+1 (diag-only mask)
__global__ void __launch_bounds__(128) fixup_kernel(
    const float* __restrict__ v, const float* __restrict__ part,
    const float* __restrict__ qs, const float* __restrict__ ks,
    float* __restrict__ weighted)
{
    int b = blockIdx.x, which = blockIdx.y, tx = threadIdx.x;
    int r = Nn + which;
    float vsum = 0.f;
    #pragma unroll
    for (int p = 0; p < 16; ++p) vsum += part[(b*16 + p)*128 + tx];
    float s = qs[b*Cc + r] + ks[b*Cc + r];
    s = s > 0.f ? s : 0.01f*s;
    float mx = fmaxf(s, 0.f);
    float es = __expf(s - mx), e0 = __expf(-mx);
    float vr = v[((size_t)(b*Cc + r))*128 + tx];
    float denom = es + (float)(Cc - 1) * e0;
    weighted[((size_t)(b*Cc + r))*128 + tx] = (es*vr + e0*(vsum - vr)) / denom;
}

__global__ void __launch_bounds__(128) mean1_kernel(const float* __restrict__ f, float* __restrict__ part){
    int b = blockIdx.x, p = blockIdx.y, tx = threadIdx.x;
    float s = 0.f;
    #pragma unroll 8
    for (int i = 0; i < Cc/16; ++i) s += f[((size_t)b*Cc + p*(Cc/16) + i)*128 + tx];
    part[(b*16 + p)*128 + tx] = s;
}
__global__ void __launch_bounds__(128) mean2_kernel(const float* __restrict__ part, float* __restrict__ out){
    int b = blockIdx.x, tx = threadIdx.x;
    float s = 0.f;
    #pragma unroll
    for (int p = 0; p < 16; ++p) s += part[(b*16 + p)*128 + tx];
    out[b*128 + tx] = s * (1.f/Cc);
}

extern "C" void kernel_launch(void* const* d_in, const int* in_sizes, int n_in,
                              void* d_out, int out_size)
{
    const float* ops       = (const float*)d_in[0];
    const float* mask      = (const float*)d_in[1];
    const int*   relations = (const int*)d_in[2];
    const int*   begins    = (const int*)d_in[3];
    const int*   ends      = (const int*)d_in[4];
    const float* init_bp_w = (const float*)d_in[5];
    const float* init_bp_b = (const float*)d_in[6];
    const float* init_ep_w = (const float*)d_in[7];
    const float* init_ep_b = (const float*)d_in[8];
    const float* be_bp_w   = (const float*)d_in[9];
    const float* be_bp_b   = (const float*)d_in[10];
    const float* be_ep_w   = (const float*)d_in[11];
    const float* be_ep_b   = (const float*)d_in[12];
    const float* seq_mix_w = (const float*)d_in[13];
    const float* seq_mix_b = (const float*)d_in[14];
    const float* attn_w_w  = (const float*)d_in[15];
    const float* attn_w_b  = (const float*)d_in[16];
    const float* score_w   = (const float*)d_in[17];
    const float* score_b   = (const float*)d_in[18];
    const float* attn_out_w= (const float*)d_in[19];
    const float* attn_out_b= (const float*)d_in[20];
    const float* mix_w     = (const float*)d_in[21];
    const float* mix_b     = (const float*)d_in[22];
    float* out = (float*)d_out;

    float *p_f0,*p_f1,*p_v,*p_seq,*p_wt,*p_ao,*p_qs,*p_ks,*p_uq,*p_uk,*p_c,*p_part,*p_km,*p_num,*p_den;
    cudaGetSymbolAddress((void**)&p_f0, g_feats0);
    cudaGetSymbolAddress((void**)&p_f1, g_feats1);
    cudaGetSymbolAddress((void**)&p_v,  g_v);
    cudaGetSymbolAddress((void**)&p_seq, g_seq);
    cudaGetSymbolAddress((void**)&p_wt, g_weighted);
    cudaGetSymbolAddress((void**)&p_ao, g_attnout);
    cudaGetSymbolAddress((void**)&p_qs, g_qs);
    cudaGetSymbolAddress((void**)&p_ks, g_ks);
    cudaGetSymbolAddress((void**)&p_uq, g_uq);
    cudaGetSymbolAddress((void**)&p_uk, g_uk);
    cudaGetSymbolAddress((void**)&p_c,  g_c);
    cudaGetSymbolAddress((void**)&p_part, g_part);
    cudaGetSymbolAddress((void**)&p_km, g_ksmax);
    cudaGetSymbolAddress((void**)&p_num, g_num);
    cudaGetSymbolAddress((void**)&p_den, g_den);

    copy_ops_kernel<<<(BN*Dd)/256, 256>>>(ops, p_f0);
    begin_end_kernel<<<dim3(Bb,2), 128>>>(p_f0, begins, ends,
        init_bp_w, init_bp_b, init_ep_w, init_ep_b, p_f0);

    for (int l = 0; l < Ll; ++l) {
        float* cur = (l == 0) ? p_f0 : p_f1;
        float* nxt = (l == 0) ? p_f1 : p_f0;

        precompute_kernel<<<1, 128>>>(attn_w_w + (size_t)l*128*384, attn_w_b + (size_t)l*384,
                                      score_w + (size_t)l*256, score_b + l, p_uq, p_uk, p_c);
        qsks_kernel<<<BC/8, 256>>>(cur, p_uq, p_uk, p_c, p_qs, p_ks);
        ksmax_kernel<<<Bb, 256>>>(p_ks, p_km);

        gemm_mma_kernel<0,128><<<dim3(BC/128,2), 256>>>(cur, nullptr,
            attn_w_w + (size_t)l*128*384 + 256, 384, attn_w_b + (size_t)l*384 + 256,
            p_v, nullptr);
        mean1_kernel<<<dim3(Bb,16), 128>>>(p_v, p_part);   // V column partial sums

        begin_end_kernel<<<dim3(Bb,2), 128>>>(cur, begins, ends,
            be_bp_w + (size_t)l*128*128, be_bp_b + (size_t)l*128,
            be_ep_w + (size_t)l*128*128, be_ep_b + (size_t)l*128, p_seq);

        gemm_mma_kernel<1,384><<<dim3(BC/128,2), 256>>>(cur, nullptr,
            seq_mix_w + (size_t)l*384*128, 128, seq_mix_b + (size_t)l*128,
            p_seq, relations);

        attn_mma_kernel<<<dim3(32, Bb), 256>>>(p_v, p_qs, p_ks, p_km, mask, p_num, p_den);
        combine_kernel<<<(BC*Dd)/256, 256>>>(p_num, p_den, p_wt);
        fixup_kernel<<<dim3(Bb,2), 128>>>(p_v, p_part, p_qs, p_ks, p_wt);

        gemm_mma_kernel<0,128><<<dim3(BC/128,2), 256>>>(p_wt, nullptr,
            attn_out_w + (size_t)l*128*128, 128, attn_out_b + (size_t)l*128,
            p_ao, nullptr);

        gemm_mma_kernel<2,256><<<dim3(BC/128,2), 256>>>(p_seq, p_ao,
            mix_w + (size_t)l*256*128, 128, mix_b + (size_t)l*128,
            nxt, nullptr);
    }

    mean1_kernel<<<dim3(Bb,16), 128>>>(p_f0, p_part);
    mean2_kernel<<<Bb, 128>>>(p_part, out);
    copyout_kernel<<<(BC*Dd)/256, 256>>>(p_f0, out + Bb*Dd);
}

// round 9
// speedup vs baseline: 2.6530x; 1.0016x over previous
#include <cuda_runtime.h>
#include <cuda_fp16.h>
#include <math.h>
#include <stdint.h>

#define Bb 8
#define Nn 2046
#define Dd 128
#define Jj 128
#define Ll 2
#define Cc 2048
#define BC (Bb*Cc)
#define BN (Bb*Nn)

__device__ float g_feats0[BC*Dd];
__device__ float g_feats1[BC*Dd];
__device__ float g_v[BC*Dd];
__device__ float g_seq[BC*Dd];
__device__ float g_weighted[BC*Dd];
__device__ float g_attnout[BC*Dd];
__device__ float g_num[2*BC*Dd];
__device__ float g_den[2*BC];
__device__ float g_qs[BC];
__device__ float g_ks[BC];
__device__ float g_uq[Dd];
__device__ float g_uk[Dd];
__device__ float g_c[2];
__device__ float g_part[Bb*16*Dd];
__device__ float g_ksmax[Bb];

// ---- fp16 split helpers ----
__device__ __forceinline__ uint32_t packsplit(float x, float y, uint32_t& lo){
    __half hx = __float2half_rn(x), hy = __float2half_rn(y);
    __half lx = __float2half_rn(x - __half2float(hx));
    __half ly = __float2half_rn(y - __half2float(hy));
    __half2 h = __halves2half2(hx, hy), l2 = __halves2half2(lx, ly);
    lo = *(uint32_t*)&l2;
    return *(uint32_t*)&h;
}
__device__ __forceinline__ void mma_f16(float c[4], const uint32_t a[4], uint32_t b0, uint32_t b1){
    asm volatile("mma.sync.aligned.m16n8k16.row.col.f32.f16.f16.f32 "
        "{%0,%1,%2,%3}, {%4,%5,%6,%7}, {%8,%9}, {%0,%1,%2,%3};"
        : "+f"(c[0]), "+f"(c[1]), "+f"(c[2]), "+f"(c[3])
        : "r"(a[0]), "r"(a[1]), "r"(a[2]), "r"(a[3]), "r"(b0), "r"(b1));
}

__global__ void copy_ops_kernel(const float* __restrict__ ops, float* __restrict__ feats){
    int idx = blockIdx.x * 256 + threadIdx.x;
    int b = idx / (Nn*Dd);
    int rem = idx - b*(Nn*Dd);
    feats[(size_t)b*Cc*Dd + rem] = ops[idx];
}
__global__ void copyout_kernel(const float* __restrict__ f, float* __restrict__ o){
    size_t i = (size_t)blockIdx.x * 256 + threadIdx.x; o[i] = f[i];
}

__global__ void __launch_bounds__(128) begin_end_kernel(
    const float* __restrict__ src, const int* __restrict__ bidx, const int* __restrict__ eidx,
    const float* __restrict__ Wb, const float* __restrict__ bb,
    const float* __restrict__ We, const float* __restrict__ be, float* __restrict__ dst){
    int b = blockIdx.x, which = blockIdx.y, tx = threadIdx.x;
    const int* idx = which ? eidx : bidx;
    const float* W = which ? We : Wb;
    const float* bias = which ? be : bb;
    __shared__ float avg[128];
    float s = 0.f;
    #pragma unroll 8
    for (int j = 0; j < Jj; ++j) s += src[((size_t)b*Cc + idx[b*Jj + j])*Dd + tx];
    avg[tx] = s * (1.f/Jj);
    __syncthreads();
    float o = 0.f;
    #pragma unroll 8
    for (int dd = 0; dd < Dd; ++dd) o += avg[dd] * W[dd*Dd + tx];
    dst[((size_t)b*Cc + Nn + which)*Dd + tx] = o + bias[tx];
}

__global__ void __launch_bounds__(128) precompute_kernel(
    const float* __restrict__ aw, const float* __restrict__ ab,
    const float* __restrict__ sw, const float* __restrict__ sb,
    float* __restrict__ uq, float* __restrict__ uk, float* __restrict__ cv){
    int d = threadIdx.x;
    float s1 = 0.f, s2 = 0.f;
    #pragma unroll 8
    for (int e = 0; e < 128; ++e) {
        s1 += aw[d*384 + e] * sw[e];
        s2 += aw[d*384 + 128 + e] * sw[128 + e];
    }
    uq[d] = s1; uk[d] = s2;
    if (d == 0) {
        float c1 = 0.f, c2 = 0.f;
        for (int e = 0; e < 128; ++e) { c1 += ab[e]*sw[e]; c2 += ab[128+e]*sw[128+e]; }
        cv[0] = c1; cv[1] = c2 + sb[0];
    }
}

__global__ void __launch_bounds__(256) qsks_kernel(
    const float* __restrict__ feats, const float* __restrict__ uq, const float* __restrict__ uk,
    const float* __restrict__ cv, float* __restrict__ qs, float* __restrict__ ks){
    int warp = threadIdx.x >> 5, lane = threadIdx.x & 31;
    int m = blockIdx.x * 8 + warp;
    float4 f = ((const float4*)(feats + (size_t)m*Dd))[lane];
    float4 q4 = ((const float4*)uq)[lane];
    float4 k4 = ((const float4*)uk)[lane];
    float dq = f.x*q4.x + f.y*q4.y + f.z*q4.z + f.w*q4.w;
    float dk = f.x*k4.x + f.y*k4.y + f.z*k4.z + f.w*k4.w;
    #pragma unroll
    for (int off = 16; off; off >>= 1) {
        dq += __shfl_down_sync(0xffffffffu, dq, off);
        dk += __shfl_down_sync(0xffffffffu, dk, off);
    }
    if (lane == 0) { qs[m] = dq + cv[0]; ks[m] = dk + cv[1]; }
}

__global__ void __launch_bounds__(256) ksmax_kernel(const float* __restrict__ ks, float* __restrict__ km){
    int b = blockIdx.x, tx = threadIdx.x;
    __shared__ float sm[256];
    float m = -1e30f;
    for (int j = tx; j < Cc; j += 256) m = fmaxf(m, ks[b*Cc + j]);
    sm[tx] = m; __syncthreads();
    for (int s = 128; s; s >>= 1) { if (tx < s) sm[tx] = fmaxf(sm[tx], sm[tx+s]); __syncthreads(); }
    if (tx == 0) km[b] = sm[0];
}

// ======== fp16 mma GEMM, pipelined: 128 rows x 64 outs, col-split x2, 256 thr ========
#define PST2 72
#define ASTRIDE 36

template<int MODE, int KTOT>
__global__ void __launch_bounds__(256) gemm_mma_kernel(
    const float* __restrict__ A, const float* __restrict__ A2,
    const float* __restrict__ W, int ws, const float* __restrict__ bias,
    float* __restrict__ out, const int* __restrict__ relations)
{
    __shared__ float As[128*ASTRIDE];
    __shared__ uint32_t Wph[16*PST2];
    __shared__ uint32_t Wpl[16*PST2];
    __shared__ int s_src[3][128];
    __shared__ int s_out[128];

    const int tid = threadIdx.x, w = tid>>5, lane = tid&31;
    const int g = lane>>2, l = lane&3;
    const int m0 = blockIdx.x * 128;
    const int c0 = blockIdx.y * 64;

    if (tid < 128) {
        int m = m0 + tid;
        if (MODE == 1) {
            int b = m >> 11;
            int i = m & 2047;
            if (i < Nn) {
                s_src[0][tid] = b*Cc + i;
                int rp = relations[(size_t)(b*Nn + i)*2 + 0];
                int rs = relations[(size_t)(b*Nn + i)*2 + 1];
                s_src[1][tid] = b*Cc + (rp < 0 ? Nn : rp);
                s_src[2][tid] = b*Cc + (rs < 0 ? Nn + 1 : rs);
                s_out[tid] = m;
            } else {
                s_src[0][tid] = b*Cc; s_src[1][tid] = b*Cc; s_src[2][tid] = b*Cc;
                s_out[tid] = -1;
            }
        } else {
            s_out[tid] = m;
        }
    }
    if (MODE == 1) __syncthreads();   // s_src needed by prologue loads

    float acc[8][4];
    #pragma unroll
    for (int nt = 0; nt < 8; ++nt) {
        acc[nt][0]=0.f; acc[nt][1]=0.f; acc[nt][2]=0.f; acc[nt][3]=0.f;
    }

    const int pr = tid>>4, cb4 = (tid&15)*4;
    const int ar = tid>>1, ao = (tid&1)*16;

    // ---- prefetch registers ----
    float4 wA, wB, a0, a1, a2, a3;

    auto loadW = [&](int k0, float4& ra, float4& rb){
        const float* wa = W + (size_t)(k0 + 2*pr)*ws + c0 + cb4;
        ra = *(const float4*)wa;
        rb = *(const float4*)(wa + ws);
    };
    auto loadA = [&](int k0, float4& r0, float4& r1, float4& r2, float4& r3){
        const float* asrc;
        if (MODE == 0) {
            asrc = A + (size_t)(m0 + ar)*128 + k0 + ao;
        } else if (MODE == 1) {
            int seg = k0 >> 7, col = k0 & 127;
            asrc = A + (size_t)s_src[seg][ar]*128 + col + ao;
        } else {
            int seg = k0 >> 7, col = k0 & 127;
            const float* base = seg ? A2 : A;
            asrc = base + (size_t)(m0 + ar)*128 + col + ao;
        }
        r0 = *(const float4*)(asrc + 0);
        r1 = *(const float4*)(asrc + 4);
        r2 = *(const float4*)(asrc + 8);
        r3 = *(const float4*)(asrc + 12);
    };

    loadW(0, wA, wB);
    loadA(0, a0, a1, a2, a3);

    for (int k0 = 0; k0 < KTOT; k0 += 32) {
        __syncthreads();
        {   // STS packed W
            uint32_t* dh = Wph + pr*PST2 + cb4;
            uint32_t* dl = Wpl + pr*PST2 + cb4;
            uint32_t lo;
            dh[0] = packsplit(wA.x, wB.x, lo); dl[0] = lo;
            dh[1] = packsplit(wA.y, wB.y, lo); dl[1] = lo;
            dh[2] = packsplit(wA.z, wB.z, lo); dl[2] = lo;
            dh[3] = packsplit(wA.w, wB.w, lo); dl[3] = lo;
        }
        {   // STS A fp32
            float* d = As + ar*ASTRIDE + ao;
            *(float4*)(d + 0)  = a0;
            *(float4*)(d + 4)  = a1;
            *(float4*)(d + 8)  = a2;
            *(float4*)(d + 12) = a3;
        }
        __syncthreads();

        if (k0 + 32 < KTOT) {   // prefetch next tile (overlaps mma below)
            loadW(k0 + 32, wA, wB);
            loadA(k0 + 32, a0, a1, a2, a3);
        }

        #pragma unroll
        for (int kc = 0; kc < 2; ++kc) {
            const float* ap  = As + (16*w + g)*ASTRIDE + kc*16;
            const float* ap8 = ap + 8*ASTRIDE;
            float2 x0 = *(const float2*)(ap  + 2*l);
            float2 x1 = *(const float2*)(ap8 + 2*l);
            float2 x2 = *(const float2*)(ap  + 2*l + 8);
            float2 x3 = *(const float2*)(ap8 + 2*l + 8);
            uint32_t ah[4], al[4];
            ah[0] = packsplit(x0.x, x0.y, al[0]);
            ah[1] = packsplit(x1.x, x1.y, al[1]);
            ah[2] = packsplit(x2.x, x2.y, al[2]);
            ah[3] = packsplit(x3.x, x3.y, al[3]);
            const uint32_t* ph  = Wph + (kc*8 + l)*PST2;
            const uint32_t* ph4 = Wph + (kc*8 + l + 4)*PST2;
            const uint32_t* pl  = Wpl + (kc*8 + l)*PST2;
            const uint32_t* pl4 = Wpl + (kc*8 + l + 4)*PST2;
            #pragma unroll
            for (int nt = 0; nt < 8; ++nt) {
                int dcol = nt*8 + g;
                uint32_t bh0 = ph[dcol],  bh1 = ph4[dcol];
                uint32_t bl0 = pl[dcol],  bl1 = pl4[dcol];
                mma_f16(acc[nt], ah, bh0, bh1);
                mma_f16(acc[nt], al, bh0, bh1);
                mma_f16(acc[nt], ah, bl0, bl1);
            }
        }
    }

    const int r0 = 16*w + g;
    const int o0 = s_out[r0], o1 = s_out[r0 + 8];
    float* w0 = out + (size_t)o0*128;
    float* w1 = out + (size_t)o1*128;
    #pragma unroll
    for (int nt = 0; nt < 8; ++nt) {
        int col = c0 + nt*8 + 2*l;
        float b0 = __ldg(bias + col), b1 = __ldg(bias + col + 1);
        if (o0 >= 0) *(float2*)(w0 + col) = make_float2(acc[nt][0]+b0, acc[nt][1]+b1);
        if (o1 >= 0) *(float2*)(w1 + col) = make_float2(acc[nt][2]+b0, acc[nt][3]+b1);
    }
}

// ======== fp16 mma attention, j-split x2, pipelined: grid(32,B), 256 thr ========
#define PSTR 136
__device__ __forceinline__ float pval(float q, float M, float kv, float mv){
    float x = q + kv; x = x > 0.f ? x : 0.01f*x;
    return __expf(x*mv - M);
}
__device__ __forceinline__ float mval(const float* mrow, bool in, int gi, int j){
    return (in && j < Nn) ? __ldg(mrow + j) : ((gi == j) ? 1.f : 0.f);
}

__global__ void __launch_bounds__(256) attn_mma_kernel(
    const float* __restrict__ v, const float* __restrict__ qs,
    const float* __restrict__ ks, const float* __restrict__ ksmax,
    const float* __restrict__ mask, float* __restrict__ num, float* __restrict__ den)
{
    __shared__ uint32_t Vph[16*PSTR];
    __shared__ uint32_t Vpl[16*PSTR];
    __shared__ float s_ks[32];

    const int b = blockIdx.y;
    const int jc = blockIdx.x & 1;
    const int i0 = (blockIdx.x >> 1) * 128;
    const int tid = threadIdx.x, w = tid>>5, lane = tid&31;
    const int g = lane>>2, l = lane&3;
    const int r0 = 16*w + g, r1 = r0 + 8;
    const int gi0 = i0 + r0, gi1 = i0 + r1;

    const float q0 = qs[b*Cc + gi0];
    const float q1 = qs[b*Cc + gi1];
    const float km = ksmax[b];
    float t0 = q0 + km; t0 = t0 > 0.f ? t0 : 0.01f*t0;
    float t1 = q1 + km; t1 = t1 > 0.f ? t1 : 0.01f*t1;
    const float M0 = fmaxf(0.f, t0);
    const float M1 = fmaxf(0.f, t1);
    float sum0 = 0.f, sum1 = 0.f;

    const float* mrow0 = mask + (size_t)b*Nn*Nn + (size_t)gi0*Nn;
    const float* mrow1 = mask + (size_t)b*Nn*Nn + (size_t)gi1*Nn;
    const bool in0 = gi0 < Nn, in1 = gi1 < Nn;

    float acc[16][4];
    #pragma unroll
    for (int nt = 0; nt < 16; ++nt) {
        acc[nt][0]=0.f; acc[nt][1]=0.f; acc[nt][2]=0.f; acc[nt][3]=0.f;
    }

    const int pr = tid>>4, cb = (tid&15)*8;
    const int jbeg = jc * 1024, jend = jbeg + 1024;

    float4 va0, va1, vb0, vb1;
    float ksr = 0.f;
    auto loadV = [&](int j0){
        const float* va = v + ((size_t)(b*Cc + j0 + 2*pr))*128 + cb;
        va0 = *(const float4*)va;      va1 = *(const float4*)(va + 4);
        vb0 = *(const float4*)(va+128); vb1 = *(const float4*)(va + 132);
        if (tid < 32) ksr = ks[b*Cc + j0 + tid];
    };
    loadV(jbeg);

    for (int j0 = jbeg; j0 < jend; j0 += 32) {
        __syncthreads();
        {   // STS packed V + ks
            uint32_t* dh = Vph + pr*PSTR + cb;
            uint32_t* dl = Vpl + pr*PSTR + cb;
            uint32_t lo;
            dh[0] = packsplit(va0.x, vb0.x, lo); dl[0] = lo;
            dh[1] = packsplit(va0.y, vb0.y, lo); dl[1] = lo;
            dh[2] = packsplit(va0.z, vb0.z, lo); dl[2] = lo;
            dh[3] = packsplit(va0.w, vb0.w, lo); dl[3] = lo;
            dh[4] = packsplit(va1.x, vb1.x, lo); dl[4] = lo;
            dh[5] = packsplit(va1.y, vb1.y, lo); dl[5] = lo;
            dh[6] = packsplit(va1.z, vb1.z, lo); dl[6] = lo;
            dh[7] = packsplit(va1.w, vb1.w, lo); dl[7] = lo;
            if (tid < 32) s_ks[tid] = ksr;
        }
        __syncthreads();

        if (j0 + 32 < jend) loadV(j0 + 32);   // prefetch (overlaps below)

        // hoisted mask loads (MLP=16)
        float m0v[8], m1v[8];
        #pragma unroll
        for (int kc = 0; kc < 2; ++kc) {
            int ja = j0 + kc*16 + 2*l;
            m0v[kc*4+0] = mval(mrow0, in0, gi0, ja);
            m0v[kc*4+1] = mval(mrow0, in0, gi0, ja+1);
            m0v[kc*4+2] = mval(mrow0, in0, gi0, ja+8);
            m0v[kc*4+3] = mval(mrow0, in0, gi0, ja+9);
            m1v[kc*4+0] = mval(mrow1, in1, gi1, ja);
            m1v[kc*4+1] = mval(mrow1, in1, gi1, ja+1);
            m1v[kc*4+2] = mval(mrow1, in1, gi1, ja+8);
            m1v[kc*4+3] = mval(mrow1, in1, gi1, ja+9);
        }

        #pragma unroll
        for (int kc = 0; kc < 2; ++kc) {
            const int kb = kc*16 + 2*l;
            const float kv0 = s_ks[kb],   kv1 = s_ks[kb+1];
            const float kv8 = s_ks[kb+8], kv9 = s_ks[kb+9];
            float p00 = pval(q0, M0, kv0, m0v[kc*4+0]);
            float p01 = pval(q0, M0, kv1, m0v[kc*4+1]);
            float p08 = pval(q0, M0, kv8, m0v[kc*4+2]);
            float p09 = pval(q0, M0, kv9, m0v[kc*4+3]);
            float p10 = pval(q1, M1, kv0, m1v[kc*4+0]);
            float p11 = pval(q1, M1, kv1, m1v[kc*4+1]);
            float p18 = pval(q1, M1, kv8, m1v[kc*4+2]);
            float p19 = pval(q1, M1, kv9, m1v[kc*4+3]);
            sum0 += p00 + p01 + p08 + p09;
            sum1 += p10 + p11 + p18 + p19;
            uint32_t ah[4], al[4];
            ah[0] = packsplit(p00, p01, al[0]);
            ah[1] = packsplit(p10, p11, al[1]);
            ah[2] = packsplit(p08, p09, al[2]);
            ah[3] = packsplit(p18, p19, al[3]);
            const uint32_t* ph  = Vph + (kc*8 + l)*PSTR;
            const uint32_t* ph4 = Vph + (kc*8 + l + 4)*PSTR;
            const uint32_t* pl  = Vpl + (kc*8 + l)*PSTR;
            const uint32_t* pl4 = Vpl + (kc*8 + l + 4)*PSTR;
            #pragma unroll
            for (int nt = 0; nt < 16; ++nt) {
                int dcol = nt*8 + g;
                uint32_t bh0 = ph[dcol],  bh1 = ph4[dcol];
                uint32_t bl0 = pl[dcol],  bl1 = pl4[dcol];
                mma_f16(acc[nt], ah, bh0, bh1);
                mma_f16(acc[nt], al, bh0, bh1);
                mma_f16(acc[nt], ah, bl0, bl1);
            }
        }
    }

    sum0 += __shfl_xor_sync(0xffffffffu, sum0, 1);
    sum0 += __shfl_xor_sync(0xffffffffu, sum0, 2);
    sum1 += __shfl_xor_sync(0xffffffffu, sum1, 1);
    sum1 += __shfl_xor_sync(0xffffffffu, sum1, 2);
    if (l == 0) {
        den[(size_t)jc*BC + b*Cc + gi0] = sum0;
        den[(size_t)jc*BC + b*Cc + gi1] = sum1;
    }

    float* n0 = num + (size_t)jc*BC*Dd + ((size_t)(b*Cc + gi0))*128;
    float* n1 = num + (size_t)jc*BC*Dd + ((size_t)(b*Cc + gi1))*128;
    #pragma unroll
    for (int nt = 0; nt < 16; ++nt) {
        int col = nt*8 + 2*l;
        *(float2*)(n0 + col) = make_float2(acc[nt][0], acc[nt][1]);
        *(float2*)(n1 + col) = make_float2(acc[nt][2], acc[nt][3]);
    }
}

// combine j-split partials: wt = (num0+num1)/(den0+den1)
__global__ void __launch_bounds__(256) combine_kernel(
    const float* __restrict__ num, const float* __restrict__ den,
    float* __restrict__ wt)
{
    size_t idx = (size_t)blockIdx.x*256 + threadIdx.x;
    int m = (int)(idx >> 7);
    float d = den[m] + den[BC + m];
    wt[idx] = (num[idx] + num[(size_t)BC*Dd + idx]) / d;
}

// exact fp32 recompute of attention rows N, N+1 (diag-only mask)
__global__ void __launch_bounds__(128) fixup_kernel(
    const float* __restrict__ v, const float* __restrict__ part,
    const float* __restrict__ qs, const float* __restrict__ ks,
    float* __restrict__ weighted)
{
    int b = blockIdx.x, which = blockIdx.y, tx = threadIdx.x;
    int r = Nn + which;
    float vsum = 0.f;
    #pragma unroll
    for (int p = 0; p < 16; ++p) vsum += part[(b*16 + p)*128 + tx];
    float s = qs[b*Cc + r] + ks[b*Cc + r];
    s = s > 0.f ? s : 0.01f*s;
    float mx = fmaxf(s, 0.f);
    float es = __expf(s - mx), e0 = __expf(-mx);
    float vr = v[((size_t)(b*Cc + r))*128 + tx];
    float denom = es + (float)(Cc - 1) * e0;
    weighted[((size_t)(b*Cc + r))*128 + tx] = (es*vr + e0*(vsum - vr)) / denom;
}

__global__ void __launch_bounds__(128) mean1_kernel(const float* __restrict__ f, float* __restrict__ part){
    int b = blockIdx.x, p = blockIdx.y, tx = threadIdx.x;
    float s = 0.f;
    #pragma unroll 8
    for (int i = 0; i < Cc/16; ++i) s += f[((size_t)b*Cc + p*(Cc/16) + i)*128 + tx];
    part[(b*16 + p)*128 + tx] = s;
}
__global__ void __launch_bounds__(128) mean2_kernel(const float* __restrict__ part, float* __restrict__ out){
    int b = blockIdx.x, tx = threadIdx.x;
    float s = 0.f;
    #pragma unroll
    for (int p = 0; p < 16; ++p) s += part[(b*16 + p)*128 + tx];
    out[b*128 + tx] = s * (1.f/Cc);
}

extern "C" void kernel_launch(void* const* d_in, const int* in_sizes, int n_in,
                              void* d_out, int out_size)
{
    const float* ops       = (const float*)d_in[0];
    const float* mask      = (const float*)d_in[1];
    const int*   relations = (const int*)d_in[2];
    const int*   begins    = (const int*)d_in[3];
    const int*   ends      = (const int*)d_in[4];
    const float* init_bp_w = (const float*)d_in[5];
    const float* init_bp_b = (const float*)d_in[6];
    const float* init_ep_w = (const float*)d_in[7];
    const float* init_ep_b = (const float*)d_in[8];
    const float* be_bp_w   = (const float*)d_in[9];
    const float* be_bp_b   = (const float*)d_in[10];
    const float* be_ep_w   = (const float*)d_in[11];
    const float* be_ep_b   = (const float*)d_in[12];
    const float* seq_mix_w = (const float*)d_in[13];
    const float* seq_mix_b = (const float*)d_in[14];
    const float* attn_w_w  = (const float*)d_in[15];
    const float* attn_w_b  = (const float*)d_in[16];
    const float* score_w   = (const float*)d_in[17];
    const float* score_b   = (const float*)d_in[18];
    const float* attn_out_w= (const float*)d_in[19];
    const float* attn_out_b= (const float*)d_in[20];
    const float* mix_w     = (const float*)d_in[21];
    const float* mix_b     = (const float*)d_in[22];
    float* out = (float*)d_out;

    float *p_f0,*p_f1,*p_v,*p_seq,*p_wt,*p_ao,*p_qs,*p_ks,*p_uq,*p_uk,*p_c,*p_part,*p_km,*p_num,*p_den;
    cudaGetSymbolAddress((void**)&p_f0, g_feats0);
    cudaGetSymbolAddress((void**)&p_f1, g_feats1);
    cudaGetSymbolAddress((void**)&p_v,  g_v);
    cudaGetSymbolAddress((void**)&p_seq, g_seq);
    cudaGetSymbolAddress((void**)&p_wt, g_weighted);
    cudaGetSymbolAddress((void**)&p_ao, g_attnout);
    cudaGetSymbolAddress((void**)&p_qs, g_qs);
    cudaGetSymbolAddress((void**)&p_ks, g_ks);
    cudaGetSymbolAddress((void**)&p_uq, g_uq);
    cudaGetSymbolAddress((void**)&p_uk, g_uk);
    cudaGetSymbolAddress((void**)&p_c,  g_c);
    cudaGetSymbolAddress((void**)&p_part, g_part);
    cudaGetSymbolAddress((void**)&p_km, g_ksmax);
    cudaGetSymbolAddress((void**)&p_num, g_num);
    cudaGetSymbolAddress((void**)&p_den, g_den);

    copy_ops_kernel<<<(BN*Dd)/256, 256>>>(ops, p_f0);
    begin_end_kernel<<<dim3(Bb,2), 128>>>(p_f0, begins, ends,
        init_bp_w, init_bp_b, init_ep_w, init_ep_b, p_f0);

    for (int l = 0; l < Ll; ++l) {
        float* cur = (l == 0) ? p_f0 : p_f1;
        float* nxt = (l == 0) ? p_f1 : p_f0;

        precompute_kernel<<<1, 128>>>(attn_w_w + (size_t)l*128*384, attn_w_b + (size_t)l*384,
                                      score_w + (size_t)l*256, score_b + l, p_uq, p_uk, p_c);
        qsks_kernel<<<BC/8, 256>>>(cur, p_uq, p_uk, p_c, p_qs, p_ks);
        ksmax_kernel<<<Bb, 256>>>(p_ks, p_km);

        gemm_mma_kernel<0,128><<<dim3(BC/128,2), 256>>>(cur, nullptr,
            attn_w_w + (size_t)l*128*384 + 256, 384, attn_w_b + (size_t)l*384 + 256,
            p_v, nullptr);
        mean1_kernel<<<dim3(Bb,16), 128>>>(p_v, p_part);

        begin_end_kernel<<<dim3(Bb,2), 128>>>(cur, begins, ends,
            be_bp_w + (size_t)l*128*128, be_bp_b + (size_t)l*128,
            be_ep_w + (size_t)l*128*128, be_ep_b + (size_t)l*128, p_seq);

        gemm_mma_kernel<1,384><<<dim3(BC/128,2), 256>>>(cur, nullptr,
            seq_mix_w + (size_t)l*384*128, 128, seq_mix_b + (size_t)l*128,
            p_seq, relations);

        attn_mma_kernel<<<dim3(32, Bb), 256>>>(p_v, p_qs, p_ks, p_km, mask, p_num, p_den);
        combine_kernel<<<(BC*Dd)/256, 256>>>(p_num, p_den, p_wt);
        fixup_kernel<<<dim3(Bb,2), 128>>>(p_v, p_part, p_qs, p_ks, p_wt);

        gemm_mma_kernel<0,128><<<dim3(BC/128,2), 256>>>(p_wt, nullptr,
            attn_out_w + (size_t)l*128*128, 128, attn_out_b + (size_t)l*128,
            p_ao, nullptr);

        gemm_mma_kernel<2,256><<<dim3(BC/128,2), 256>>>(p_seq, p_ao,
            mix_w + (size_t)l*256*128, 128, mix_b + (size_t)l*128,
            nxt, nullptr);
    }

    mean1_kernel<<<dim3(Bb,16), 128>>>(p_f0, p_part);
    mean2_kernel<<<Bb, 128>>>(p_part, out);
    copyout_kernel<<<(BC*Dd)/256, 256>>>(p_f0, out + Bb*Dd);
}